// round 1
// baseline (speedup 1.0000x reference)
#include <cuda_runtime.h>
#include <math.h>

#define M_TOTAL 16384
#define D_DIM   2048
#define DI_DIM  256
#define L_SEQ   4096
#define LN_EPS  1e-5f

// Scratch (channel-major / transposed layouts so the scan is fully coalesced)
__device__ float g_z [DI_DIM * M_TOTAL];   // z^T   [256][16384]
__device__ float g_dg[1024   * M_TOTAL];   // dg^T  [1024][16384]  (delta/gate, both dirs)
__device__ float g_h [512    * M_TOTAL];   // h^T   [512][16384]   (h_fwd | h_bwd)
__device__ float g_out[(size_t)M_TOTAL * D_DIM]; // y = out + x, row-major

// ---------------------------------------------------------------------------
// Generic fp32 tiled GEMM: C = A*B, tiles 128x128x16, 256 threads, 8x8/thread.
// A_KMAJOR: A stored [K][M] (K-major) else [M][K] (row-major).
// B: row-major [K][N]; columns < split come from B0 (row width=split),
//    columns >= split from B1 (row width = N-split).
// MODE 0: C[m*N+c]            (row-major store)
// MODE 1: C[c*M+m]            (transposed store)
// MODE 2: transposed store with delta/gate epilogue (EX = z^T)
// MODE 3: C[m*N+c] = acc + EX[m*N+c]  (fused residual)
// ---------------------------------------------------------------------------
template<int MODE, bool A_KMAJOR>
__global__ __launch_bounds__(256)
void gemm128(const float* __restrict__ A,
             const float* __restrict__ B0,
             const float* __restrict__ B1,
             float* __restrict__ C,
             const float* __restrict__ EX,
             int N, int K, int split)
{
    const int BM = 128, BN = 128, BK = 16;
    __shared__ float As[BK][BM + 4];
    __shared__ float Bs[BK][BN + 4];

    int tid = threadIdx.x;
    int m0 = blockIdx.y * BM;
    int n0 = blockIdx.x * BN;
    int ty = tid >> 4, tx = tid & 15;
    int mrow = ty * 8, ncol = tx * 8;

    float acc[8][8];
#pragma unroll
    for (int i = 0; i < 8; i++)
#pragma unroll
        for (int j = 0; j < 8; j++) acc[i][j] = 0.f;

    for (int k0 = 0; k0 < K; k0 += BK) {
        // ---- load A tile into As[k][m] ----
        if (A_KMAJOR) {
#pragma unroll
            for (int r = 0; r < 2; r++) {
                int idx = tid + r * 256;
                int kr = idx >> 5;            // 0..15
                int mc = (idx & 31) << 2;     // 0..124
                float4 v = *(const float4*)&A[(size_t)(k0 + kr) * M_TOTAL + m0 + mc];
                *(float4*)&As[kr][mc] = v;
            }
        } else {
#pragma unroll
            for (int r = 0; r < 2; r++) {
                int idx = tid + r * 256;
                int row = idx >> 2;           // 0..127
                int kc = (idx & 3) << 2;      // 0,4,8,12
                float4 v = *(const float4*)&A[(size_t)(m0 + row) * K + k0 + kc];
                As[kc + 0][row] = v.x;
                As[kc + 1][row] = v.y;
                As[kc + 2][row] = v.z;
                As[kc + 3][row] = v.w;
            }
        }
        // ---- load B tile into Bs[k][c] ----
#pragma unroll
        for (int r = 0; r < 2; r++) {
            int idx = tid + r * 256;
            int kr = idx >> 5;
            int cc = (idx & 31) << 2;
            int c = n0 + cc;
            float4 v;
            if (c < split)
                v = *(const float4*)&B0[(size_t)(k0 + kr) * split + c];
            else
                v = *(const float4*)&B1[(size_t)(k0 + kr) * (N - split) + (c - split)];
            *(float4*)&Bs[kr][cc] = v;
        }
        __syncthreads();

#pragma unroll
        for (int k = 0; k < BK; k++) {
            float a[8], b[8];
            *(float4*)&a[0] = *(const float4*)&As[k][mrow];
            *(float4*)&a[4] = *(const float4*)&As[k][mrow + 4];
            *(float4*)&b[0] = *(const float4*)&Bs[k][ncol];
            *(float4*)&b[4] = *(const float4*)&Bs[k][ncol + 4];
#pragma unroll
            for (int i = 0; i < 8; i++)
#pragma unroll
                for (int j = 0; j < 8; j++)
                    acc[i][j] = fmaf(a[i], b[j], acc[i][j]);
        }
        __syncthreads();
    }

    // ---- epilogue ----
    if (MODE == 0 || MODE == 3) {
#pragma unroll
        for (int i = 0; i < 8; i++) {
            int m = m0 + mrow + i;
#pragma unroll
            for (int j = 0; j < 8; j += 4) {
                float4 v = make_float4(acc[i][j], acc[i][j + 1], acc[i][j + 2], acc[i][j + 3]);
                size_t off = (size_t)m * N + n0 + ncol + j;
                if (MODE == 3) {
                    float4 r = *(const float4*)&EX[off];
                    v.x += r.x; v.y += r.y; v.z += r.z; v.w += r.w;
                }
                *(float4*)&C[off] = v;
            }
        }
    } else {
#pragma unroll
        for (int j = 0; j < 8; j++) {
            int c = n0 + ncol + j;
            float vals[8];
#pragma unroll
            for (int i = 0; i < 8; i++) vals[i] = acc[i][j];
            if (MODE == 2) {
                int jj = c & 511;
                if (jj < 256) {
#pragma unroll
                    for (int i = 0; i < 8; i++)
                        vals[i] = 1.f / (1.f + expf(-vals[i]));
                } else {
                    int ch = jj - 256;
                    const float* zp = &EX[(size_t)ch * M_TOTAL + m0 + mrow];
                    float4 z0 = *(const float4*)&zp[0];
                    float4 z1 = *(const float4*)&zp[4];
                    vals[0] *= z0.x; vals[1] *= z0.y; vals[2] *= z0.z; vals[3] *= z0.w;
                    vals[4] *= z1.x; vals[5] *= z1.y; vals[6] *= z1.z; vals[7] *= z1.w;
                }
            }
            *(float4*)&C[(size_t)c * M_TOTAL + m0 + mrow] =
                make_float4(vals[0], vals[1], vals[2], vals[3]);
            *(float4*)&C[(size_t)c * M_TOTAL + m0 + mrow + 4] =
                make_float4(vals[4], vals[5], vals[6], vals[7]);
        }
    }
}

// ---------------------------------------------------------------------------
// Gated linear scan: one block per (channel d, batch b, direction).
// h_t = delta_t * h_{t-1} + gate_t over 4096 steps.
// 256 threads x 16 contiguous elements; associative compose + Hillis-Steele.
// ---------------------------------------------------------------------------
__global__ __launch_bounds__(256)
void scan_kernel()
{
    int d = blockIdx.x, b = blockIdx.y, dir = blockIdx.z;
    const float* dptr = &g_dg[(size_t)(dir * 512 + d)       * M_TOTAL + b * L_SEQ];
    const float* gptr = &g_dg[(size_t)(dir * 512 + 256 + d) * M_TOTAL + b * L_SEQ];
    float*       hptr = &g_h [(size_t)(dir * 256 + d)       * M_TOTAL + b * L_SEQ];

    int tid = threadIdx.x;
    int base = (dir == 0) ? tid * 16 : (L_SEQ - 16 * (tid + 1));

    float tmpd[16], tmpg[16];
#pragma unroll
    for (int q = 0; q < 4; q++) {
        *(float4*)&tmpd[q * 4] = *(const float4*)&dptr[base + q * 4];
        *(float4*)&tmpg[q * 4] = *(const float4*)&gptr[base + q * 4];
    }
    float dl[16], gt[16];
#pragma unroll
    for (int e = 0; e < 16; e++) {
        int src = (dir == 0) ? e : (15 - e);
        dl[e] = tmpd[src];
        gt[e] = tmpg[src];
    }

    // local segment transform (A, B): h_out = A*h_in + B
    float Aseg = 1.f, Bseg = 0.f;
#pragma unroll
    for (int e = 0; e < 16; e++) {
        Aseg = Aseg * dl[e];
        Bseg = fmaf(Bseg, dl[e], gt[e]);
    }

    __shared__ float sA[256], sB[256];
    sA[tid] = Aseg; sB[tid] = Bseg;
    __syncthreads();
#pragma unroll
    for (int off = 1; off < 256; off <<= 1) {
        float pA = 0.f, pB = 0.f;
        bool has = (tid >= off);
        if (has) { pA = sA[tid - off]; pB = sB[tid - off]; }
        __syncthreads();
        if (has) {
            float Ac = sA[tid], Bc = sB[tid];
            sA[tid] = Ac * pA;
            sB[tid] = fmaf(Ac, pB, Bc);
        }
        __syncthreads();
    }

    float h = (tid == 0) ? 0.f : sB[tid - 1];
    float hv[16];
#pragma unroll
    for (int e = 0; e < 16; e++) {
        h = fmaf(h, dl[e], gt[e]);
        hv[e] = h;
    }

    float outv[16];
#pragma unroll
    for (int q = 0; q < 16; q++)
        outv[q] = (dir == 0) ? hv[q] : hv[15 - q];
#pragma unroll
    for (int q = 0; q < 4; q++)
        *(float4*)&hptr[base + q * 4] =
            make_float4(outv[q * 4], outv[q * 4 + 1], outv[q * 4 + 2], outv[q * 4 + 3]);
}

// ---------------------------------------------------------------------------
// LayerNorm over D=2048 per row; one block per row, 256 threads x 8 elems.
// g_out already holds y = out + x.
// ---------------------------------------------------------------------------
__global__ __launch_bounds__(256)
void ln_kernel(const float* __restrict__ gamma, const float* __restrict__ beta,
               float* __restrict__ out)
{
    int row = blockIdx.x;
    int tid = threadIdx.x;
    const float* yrow = &g_out[(size_t)row * D_DIM];

    float v[8];
    *(float4*)&v[0] = *(const float4*)&yrow[tid * 8];
    *(float4*)&v[4] = *(const float4*)&yrow[tid * 8 + 4];

    float s = 0.f, s2 = 0.f;
#pragma unroll
    for (int e = 0; e < 8; e++) { s += v[e]; s2 = fmaf(v[e], v[e], s2); }

#pragma unroll
    for (int o = 16; o > 0; o >>= 1) {
        s  += __shfl_xor_sync(0xffffffffu, s,  o);
        s2 += __shfl_xor_sync(0xffffffffu, s2, o);
    }
    __shared__ float sh[16];
    int w = tid >> 5, lane = tid & 31;
    if (lane == 0) { sh[w] = s; sh[8 + w] = s2; }
    __syncthreads();
    float S = 0.f, S2 = 0.f;
    if (lane < 8) { S = sh[lane]; S2 = sh[8 + lane]; }
#pragma unroll
    for (int o = 4; o > 0; o >>= 1) {
        S  += __shfl_xor_sync(0xffffffffu, S,  o);
        S2 += __shfl_xor_sync(0xffffffffu, S2, o);
    }
    S  = __shfl_sync(0xffffffffu, S,  0);
    S2 = __shfl_sync(0xffffffffu, S2, 0);

    const float invD = 1.f / (float)D_DIM;
    float mu = S * invD;
    float var = fmaf(S2, invD, -mu * mu);
    float inv = rsqrtf(var + LN_EPS);

    float g[8], be[8];
    *(float4*)&g[0]  = *(const float4*)&gamma[tid * 8];
    *(float4*)&g[4]  = *(const float4*)&gamma[tid * 8 + 4];
    *(float4*)&be[0] = *(const float4*)&beta[tid * 8];
    *(float4*)&be[4] = *(const float4*)&beta[tid * 8 + 4];

    float r[8];
#pragma unroll
    for (int e = 0; e < 8; e++)
        r[e] = fmaf((v[e] - mu) * inv, g[e], be[e]);

    float* orow = &out[(size_t)row * D_DIM];
    *(float4*)&orow[tid * 8]     = make_float4(r[0], r[1], r[2], r[3]);
    *(float4*)&orow[tid * 8 + 4] = make_float4(r[4], r[5], r[6], r[7]);
}

// ---------------------------------------------------------------------------
extern "C" void kernel_launch(void* const* d_in, const int* in_sizes, int n_in,
                              void* d_out, int out_size)
{
    const float* x     = (const float*)d_in[0];
    const float* W_in  = (const float*)d_in[1];
    const float* W_fwd = (const float*)d_in[2];
    const float* W_bwd = (const float*)d_in[3];
    const float* W_out = (const float*)d_in[4];
    const float* gamma = (const float*)d_in[5];
    const float* beta  = (const float*)d_in[6];
    float* out = (float*)d_out;

    float *zp, *dgp, *hp, *op;
    cudaGetSymbolAddress((void**)&zp,  g_z);
    cudaGetSymbolAddress((void**)&dgp, g_dg);
    cudaGetSymbolAddress((void**)&hp,  g_h);
    cudaGetSymbolAddress((void**)&op,  g_out);

    dim3 blk(256);

    // z^T = (x @ W_in)^T           [M=16384, N=256, K=2048]
    gemm128<1, false><<<dim3(DI_DIM / 128, M_TOTAL / 128), blk>>>(
        x, W_in, W_in, zp, nullptr, DI_DIM, D_DIM, DI_DIM);

    // dg^T = act(z @ [W_fwd|W_bwd])^T   [M, N=1024, K=256]
    gemm128<2, true><<<dim3(1024 / 128, M_TOTAL / 128), blk>>>(
        zp, W_fwd, W_bwd, dgp, zp, 1024, DI_DIM, 512);

    // bidirectional gated scans
    scan_kernel<<<dim3(DI_DIM, 4, 2), blk>>>();

    // y = h @ W_out + x            [M, N=2048, K=512]
    gemm128<3, true><<<dim3(D_DIM / 128, M_TOTAL / 128), blk>>>(
        hp, W_out, W_out, op, x, D_DIM, 512, D_DIM);

    // LayerNorm
    ln_kernel<<<M_TOTAL, blk>>>(gamma, beta, out);
}

// round 3
// speedup vs baseline: 2.4901x; 2.4901x over previous
#include <cuda_runtime.h>
#include <math.h>
#include <stdint.h>

#define M_TOTAL 16384
#define D_DIM   2048
#define DI_DIM  256
#define L_SEQ   4096
#define LN_EPS  1e-5f

// ---------------- scratch ----------------
__device__ float g_xhi[(size_t)M_TOTAL * D_DIM];
__device__ float g_xlo[(size_t)M_TOTAL * D_DIM];
__device__ float g_z  [(size_t)M_TOTAL * DI_DIM];     // z plain (gating)
__device__ float g_zhi[(size_t)M_TOTAL * DI_DIM];
__device__ float g_zlo[(size_t)M_TOTAL * DI_DIM];
__device__ float g_dg [(size_t)1024 * M_TOTAL];       // dg^T
__device__ float g_h  [(size_t)512  * M_TOTAL];       // h^T
__device__ float g_hhi[(size_t)M_TOTAL * 512];        // h row-major hi
__device__ float g_hlo[(size_t)M_TOTAL * 512];        // h row-major lo
__device__ float g_out[(size_t)M_TOTAL * D_DIM];      // y = out + x
__device__ float g_w1h[(size_t)DI_DIM * D_DIM];
__device__ float g_w1l[(size_t)DI_DIM * D_DIM];
__device__ float g_w2h[(size_t)1024 * DI_DIM];
__device__ float g_w2l[(size_t)1024 * DI_DIM];
__device__ float g_w3h[(size_t)D_DIM * 512];
__device__ float g_w3l[(size_t)D_DIM * 512];

// ---------------- arch feature gate (tcgen05 needs sm_10xa) ----------------
#if defined(__CUDA_ARCH_FEAT_SM103_ALL) || defined(__CUDA_ARCH_FEAT_SM100_ALL) || \
    defined(__CUDA_ARCH_FEAT_SM101_ALL) || defined(__CUDA_ARCH_SPECIFIC__)
#define TC_OK 1
#else
#define TC_OK 0
#endif

// ---------------- PTX helpers ----------------
__device__ __forceinline__ uint32_t smem_u32(const void* p) {
    uint32_t a;
    asm("{ .reg .u64 t; cvta.to.shared.u64 t, %1; cvt.u32.u64 %0, t; }" : "=r"(a) : "l"(p));
    return a;
}

__device__ __forceinline__ float tf32_rnd(float a) {
    uint32_t u;
    asm("cvt.rna.tf32.f32 %0, %1;" : "=r"(u) : "f"(a));
    return __uint_as_float(u);
}

#define CP_ASYNC16(dst, src) \
    asm volatile("cp.async.cg.shared.global [%0], [%1], 16;" :: "r"(dst), "l"(src))
#define CP_COMMIT() asm volatile("cp.async.commit_group;" ::: "memory")
#define CP_WAIT2()  asm volatile("cp.async.wait_group 2;" ::: "memory")

#define MBARRIER_INIT(addr, cnt) \
    asm volatile("mbarrier.init.shared.b64 [%0], %1;" :: "r"(addr), "r"(cnt) : "memory")

__device__ __forceinline__ void mbar_wait(uint32_t mbar, uint32_t parity) {
    asm volatile(
        "{\n\t.reg .pred P;\n\t"
        "W0_%=:\n\t"
        "mbarrier.try_wait.parity.acquire.cta.shared::cta.b64 P, [%0], %1, 0x989680;\n\t"
        "@P bra W1_%=;\n\t"
        "bra W0_%=;\n\t"
        "W1_%=:\n\t}"
        :: "r"(mbar), "r"(parity) : "memory");
}

#define FENCE_ASYNC_SHARED() \
    asm volatile("fence.proxy.async.shared::cta;" ::: "memory")

#if TC_OK
#define TCGEN05_ALLOC(smem_res, ncols) \
    asm volatile("tcgen05.alloc.cta_group::1.sync.aligned.shared::cta.b32 [%0], %1;" \
                 :: "r"((uint32_t)(smem_res)), "r"((uint32_t)(ncols)) : "memory")
#define TCGEN05_DEALLOC(tmem, ncols) \
    asm volatile("tcgen05.dealloc.cta_group::1.sync.aligned.b32 %0, %1;" \
                 :: "r"(tmem), "r"((uint32_t)(ncols)))
#define TCGEN05_RELINQUISH() \
    asm volatile("tcgen05.relinquish_alloc_permit.cta_group::1.sync.aligned;")
#define TCGEN05_COMMIT(mbar) \
    asm volatile("tcgen05.commit.cta_group::1.mbarrier::arrive::one.shared::cluster.b64 [%0];" \
                 :: "r"((uint32_t)(mbar)) : "memory")
#define TCGEN05_FENCE_AFTER() \
    asm volatile("tcgen05.fence::after_thread_sync;" ::: "memory")
#define TCGEN05_WAIT_LD() \
    asm volatile("tcgen05.wait::ld.sync.aligned;" ::: "memory")

#define TCGEN05_LD_X32(r, tmem_addr) \
    asm volatile( \
        "tcgen05.ld.sync.aligned.32x32b.x32.b32 " \
        "{%0, %1, %2, %3, %4, %5, %6, %7, " \
        " %8, %9, %10, %11, %12, %13, %14, %15, " \
        " %16, %17, %18, %19, %20, %21, %22, %23, " \
        " %24, %25, %26, %27, %28, %29, %30, %31}, [%32];" \
        : "=r"((r)[0]),  "=r"((r)[1]),  "=r"((r)[2]),  "=r"((r)[3]), \
          "=r"((r)[4]),  "=r"((r)[5]),  "=r"((r)[6]),  "=r"((r)[7]), \
          "=r"((r)[8]),  "=r"((r)[9]),  "=r"((r)[10]), "=r"((r)[11]), \
          "=r"((r)[12]), "=r"((r)[13]), "=r"((r)[14]), "=r"((r)[15]), \
          "=r"((r)[16]), "=r"((r)[17]), "=r"((r)[18]), "=r"((r)[19]), \
          "=r"((r)[20]), "=r"((r)[21]), "=r"((r)[22]), "=r"((r)[23]), \
          "=r"((r)[24]), "=r"((r)[25]), "=r"((r)[26]), "=r"((r)[27]), \
          "=r"((r)[28]), "=r"((r)[29]), "=r"((r)[30]), "=r"((r)[31]) \
        : "r"(tmem_addr))

// idesc kind::tf32: dtype=F32(1@4), atype=TF32(2@7), btype=TF32(2@10), N=128(16@17), M=128(8@24)
#define IDESC_TF32 ((1u << 4) | (2u << 7) | (2u << 10) | (16u << 17) | (8u << 24))

__device__ __forceinline__ void mma_tf32(uint32_t d, uint64_t ad, uint64_t bd, uint32_t en) {
    asm volatile(
        "{\n\t.reg .pred p;\n\t"
        "setp.ne.u32 p, %4, 0;\n\t"
        "tcgen05.mma.cta_group::1.kind::tf32 [%0], %1, %2, %3, {%5, %5, %5, %5}, p;\n\t}"
        :: "r"(d), "l"(ad), "l"(bd), "r"(IDESC_TF32), "r"(en), "r"(0u) : "memory");
}
#else
// compile-only stubs for the non-'a' PTX pass (never executed on device)
#define TCGEN05_ALLOC(smem_res, ncols)  do {} while (0)
#define TCGEN05_DEALLOC(tmem, ncols)    do {} while (0)
#define TCGEN05_RELINQUISH()            do {} while (0)
#define TCGEN05_COMMIT(mbar)            do {} while (0)
#define TCGEN05_FENCE_AFTER()           do {} while (0)
#define TCGEN05_WAIT_LD()               do {} while (0)
#define TCGEN05_LD_X32(r, tmem_addr) \
    do { _Pragma("unroll") for (int _i = 0; _i < 32; _i++) (r)[_i] = 0u; } while (0)
__device__ __forceinline__ void mma_tf32(uint32_t, uint64_t, uint64_t, uint32_t) {}
#endif

// SW128 K-major SMEM descriptor (layout=2, ver=1, SBO=64, LBO=1)
__device__ __forceinline__ uint64_t sdesc(uint32_t addr) {
    return 0x4000404000010000ULL | (uint64_t)((addr >> 4) & 0x3FFF);
}

// ---------------- SMEM layout for GEMM ----------------
#define STG_OFF    1024
#define STAGE_SZ   32768
#define GSMEM      (STG_OFF + 3 * STAGE_SZ)

// ---------------------------------------------------------------------------
// tcgen05 tf32 GEMM with Ootomo fp32-emulation (3 K-passes: hi*hi, hi*lo, lo*hi)
// C[M,N] = A[M,K] * Bt[N,K]^T, tiles 128x128, BK=32 per chunk.
// MODE 0: store C (plain) + Chi/Clo tf32 split     (z producer)
// MODE 2: delta/gate epilogue, transposed store into dg^T (EX = z plain)
// MODE 3: row-major store + residual EX
// ---------------------------------------------------------------------------
template<int MODE>
__global__ void __launch_bounds__(128)
gemm_tc(const float* __restrict__ Ahi, const float* __restrict__ Alo,
        const float* __restrict__ Bhi, const float* __restrict__ Blo,
        float* __restrict__ C, float* __restrict__ Chi, float* __restrict__ Clo,
        const float* __restrict__ EX, int N, int K)
{
    extern __shared__ __align__(1024) char dsm[];
    uint32_t sb = smem_u32(dsm);
    int tid = threadIdx.x, wid = tid >> 5, lane = tid & 31;
    int n0 = blockIdx.x * 128, m0 = blockIdx.y * 128;

    if (wid == 0) TCGEN05_ALLOC(sb, 128);
    if (tid == 0) {
        MBARRIER_INIT(sb + 16, 1);
        MBARRIER_INIT(sb + 24, 1);
        MBARRIER_INIT(sb + 32, 1);
    }
    __syncthreads();
    uint32_t tmem;
    asm volatile("ld.shared.b32 %0, [%1];" : "=r"(tmem) : "r"(sb));
    if (wid == 0) TCGEN05_RELINQUISH();

    const int NCk = K >> 5;        // chunks per pass
    const int NC  = 3 * NCk;       // total chunks (3 passes)
    const int k4 = tid & 7;
    const int rb = tid >> 3;

    auto load_tiles = [&](int c, int stage) {
        int p = (c >= 2 * NCk) ? 2 : ((c >= NCk) ? 1 : 0);
        int kc = (c - p * NCk) * 32;
        const float* Ap = (p == 2) ? Alo : Ahi;
        const float* Bp = (p == 1) ? Blo : Bhi;
        uint32_t sa = sb + STG_OFF + stage * STAGE_SZ;
#pragma unroll
        for (int i = 0; i < 8; i++) {
            int r = rb + 16 * i;
            uint32_t byte = r * 128 + k4 * 16;
            uint32_t sw = byte ^ ((byte >> 3) & 0x70);
            CP_ASYNC16(sa + sw, (const void*)(Ap + (size_t)(m0 + r) * K + kc + k4 * 4));
        }
#pragma unroll
        for (int i = 0; i < 8; i++) {
            int r = rb + 16 * i;
            uint32_t byte = r * 128 + k4 * 16;
            uint32_t sw = byte ^ ((byte >> 3) & 0x70);
            CP_ASYNC16(sa + 16384 + sw, (const void*)(Bp + (size_t)(n0 + r) * K + kc + k4 * 4));
        }
        CP_COMMIT();
    };

    load_tiles(0, 0);
    load_tiles(1, 1);
    load_tiles(2, 2);

    int b = 0;
    for (int c = 0; c < NC; c++) {
        CP_WAIT2();          // chunk c's stage resident (invariant: 1 commit/iter)
        __syncthreads();
        if (tid == 0) {
            FENCE_ASYNC_SHARED();
            uint32_t sa = sb + STG_OFF + b * STAGE_SZ;
            uint64_t ad = sdesc(sa), bd = sdesc(sa + 16384);
#pragma unroll
            for (int j = 0; j < 4; j++)
                mma_tf32(tmem, ad + 2 * j, bd + 2 * j, (uint32_t)((c | j) != 0));
            TCGEN05_COMMIT(sb + 16 + 8 * b);
        }
        if (c + 3 < NC) {
            mbar_wait(sb + 16 + 8 * b, (uint32_t)((c / 3) & 1));
            load_tiles(c + 3, b);
        } else {
            CP_COMMIT();     // empty group keeps wait_group accounting exact
        }
        b = (b == 2) ? 0 : b + 1;
    }
    {
        int lb = (NC - 1) % 3;
        mbar_wait(sb + 16 + 8 * lb, (uint32_t)(((NC - 1) / 3) & 1));
    }
    TCGEN05_FENCE_AFTER();

    // -------- epilogue --------
    int m = m0 + wid * 32 + lane;
    uint32_t regs[32];
#pragma unroll
    for (int cc = 0; cc < 128; cc += 32) {
        TCGEN05_LD_X32(regs, tmem + cc);
        TCGEN05_WAIT_LD();

        if (MODE == 0) {
#pragma unroll
            for (int j = 0; j < 32; j += 4) {
                size_t off = (size_t)m * N + n0 + cc + j;
                float4 v = make_float4(__uint_as_float(regs[j]),
                                       __uint_as_float(regs[j + 1]),
                                       __uint_as_float(regs[j + 2]),
                                       __uint_as_float(regs[j + 3]));
                float4 vh = make_float4(tf32_rnd(v.x), tf32_rnd(v.y),
                                        tf32_rnd(v.z), tf32_rnd(v.w));
                float4 vl = make_float4(v.x - vh.x, v.y - vh.y, v.z - vh.z, v.w - vh.w);
                *(float4*)&C[off]   = v;
                *(float4*)&Chi[off] = vh;
                *(float4*)&Clo[off] = vl;
            }
        } else if (MODE == 3) {
#pragma unroll
            for (int j = 0; j < 32; j += 4) {
                size_t off = (size_t)m * N + n0 + cc + j;
                float4 v = make_float4(__uint_as_float(regs[j]),
                                       __uint_as_float(regs[j + 1]),
                                       __uint_as_float(regs[j + 2]),
                                       __uint_as_float(regs[j + 3]));
                float4 r4 = *(const float4*)&EX[off];
                v.x += r4.x; v.y += r4.y; v.z += r4.z; v.w += r4.w;
                *(float4*)&C[off] = v;
            }
        } else {  // MODE 2: delta/gate, transposed store
            int jj0 = (n0 + cc) & 511;
            if (jj0 < 256) {
#pragma unroll
                for (int j = 0; j < 32; j++) {
                    float v = __uint_as_float(regs[j]);
                    v = 1.f / (1.f + expf(-v));
                    C[(size_t)(n0 + cc + j) * M_TOTAL + m] = v;
                }
            } else {
                int ch0 = jj0 - 256;
#pragma unroll
                for (int j = 0; j < 32; j += 4) {
                    float4 zv = *(const float4*)&EX[(size_t)m * DI_DIM + ch0 + j];
                    C[(size_t)(n0 + cc + j + 0) * M_TOTAL + m] = __uint_as_float(regs[j + 0]) * zv.x;
                    C[(size_t)(n0 + cc + j + 1) * M_TOTAL + m] = __uint_as_float(regs[j + 1]) * zv.y;
                    C[(size_t)(n0 + cc + j + 2) * M_TOTAL + m] = __uint_as_float(regs[j + 2]) * zv.z;
                    C[(size_t)(n0 + cc + j + 3) * M_TOTAL + m] = __uint_as_float(regs[j + 3]) * zv.w;
                }
            }
        }
    }

    __syncthreads();
    if (wid == 0) TCGEN05_DEALLOC(tmem, 128);
}

// ---------------------------------------------------------------------------
// elementwise tf32 split: x -> (hi, lo)
// ---------------------------------------------------------------------------
__global__ void __launch_bounds__(256)
split_kernel(const float* __restrict__ in, float* __restrict__ ohi,
             float* __restrict__ olo, size_t n4)
{
    size_t i = (size_t)blockIdx.x * blockDim.x + threadIdx.x;
    size_t stride = (size_t)gridDim.x * blockDim.x;
    for (; i < n4; i += stride) {
        float4 v = ((const float4*)in)[i];
        float4 h = make_float4(tf32_rnd(v.x), tf32_rnd(v.y), tf32_rnd(v.z), tf32_rnd(v.w));
        ((float4*)ohi)[i] = h;
        ((float4*)olo)[i] = make_float4(v.x - h.x, v.y - h.y, v.z - h.z, v.w - h.w);
    }
}

// ---------------------------------------------------------------------------
// 32x32 tiled transpose with tf32 split: in[R][C] -> hi/lo [C][R]
// ---------------------------------------------------------------------------
__global__ void __launch_bounds__(256)
transpose_split(const float* __restrict__ in, float* __restrict__ ohi,
                float* __restrict__ olo, int R, int C)
{
    __shared__ float t[32][33];
    int c0 = blockIdx.x * 32, r0 = blockIdx.y * 32;
    int tx = threadIdx.x, ty = threadIdx.y;
#pragma unroll
    for (int i = 0; i < 32; i += 8)
        t[ty + i][tx] = in[(size_t)(r0 + ty + i) * C + c0 + tx];
    __syncthreads();
#pragma unroll
    for (int i = 0; i < 32; i += 8) {
        float v = t[tx][ty + i];
        float h = tf32_rnd(v);
        size_t off = (size_t)(c0 + ty + i) * R + r0 + tx;
        ohi[off] = h;
        olo[off] = v - h;
    }
}

// ---------------------------------------------------------------------------
// Gated linear scan: block per (channel, batch, dir)
// ---------------------------------------------------------------------------
__global__ __launch_bounds__(256)
void scan_kernel()
{
    int d = blockIdx.x, bb = blockIdx.y, dir = blockIdx.z;
    const float* dptr = &g_dg[(size_t)(dir * 512 + d)       * M_TOTAL + bb * L_SEQ];
    const float* gptr = &g_dg[(size_t)(dir * 512 + 256 + d) * M_TOTAL + bb * L_SEQ];
    float*       hptr = &g_h [(size_t)(dir * 256 + d)       * M_TOTAL + bb * L_SEQ];

    int tid = threadIdx.x;
    int base = (dir == 0) ? tid * 16 : (L_SEQ - 16 * (tid + 1));

    float tmpd[16], tmpg[16];
#pragma unroll
    for (int q = 0; q < 4; q++) {
        *(float4*)&tmpd[q * 4] = *(const float4*)&dptr[base + q * 4];
        *(float4*)&tmpg[q * 4] = *(const float4*)&gptr[base + q * 4];
    }
    float dl[16], gt[16];
#pragma unroll
    for (int e = 0; e < 16; e++) {
        int src = (dir == 0) ? e : (15 - e);
        dl[e] = tmpd[src];
        gt[e] = tmpg[src];
    }

    float Aseg = 1.f, Bseg = 0.f;
#pragma unroll
    for (int e = 0; e < 16; e++) {
        Aseg = Aseg * dl[e];
        Bseg = fmaf(Bseg, dl[e], gt[e]);
    }

    __shared__ float sA[256], sB[256];
    sA[tid] = Aseg; sB[tid] = Bseg;
    __syncthreads();
#pragma unroll
    for (int off = 1; off < 256; off <<= 1) {
        float pA = 0.f, pB = 0.f;
        bool has = (tid >= off);
        if (has) { pA = sA[tid - off]; pB = sB[tid - off]; }
        __syncthreads();
        if (has) {
            float Ac = sA[tid], Bc = sB[tid];
            sA[tid] = Ac * pA;
            sB[tid] = fmaf(Ac, pB, Bc);
        }
        __syncthreads();
    }

    float h = (tid == 0) ? 0.f : sB[tid - 1];
    float hv[16];
#pragma unroll
    for (int e = 0; e < 16; e++) {
        h = fmaf(h, dl[e], gt[e]);
        hv[e] = h;
    }

    float outv[16];
#pragma unroll
    for (int q = 0; q < 16; q++)
        outv[q] = (dir == 0) ? hv[q] : hv[15 - q];
#pragma unroll
    for (int q = 0; q < 4; q++)
        *(float4*)&hptr[base + q * 4] =
            make_float4(outv[q * 4], outv[q * 4 + 1], outv[q * 4 + 2], outv[q * 4 + 3]);
}

// ---------------------------------------------------------------------------
// LayerNorm over D=2048 per row
// ---------------------------------------------------------------------------
__global__ __launch_bounds__(256)
void ln_kernel(const float* __restrict__ gamma, const float* __restrict__ beta,
               float* __restrict__ out)
{
    int row = blockIdx.x;
    int tid = threadIdx.x;
    const float* yrow = &g_out[(size_t)row * D_DIM];

    float v[8];
    *(float4*)&v[0] = *(const float4*)&yrow[tid * 8];
    *(float4*)&v[4] = *(const float4*)&yrow[tid * 8 + 4];

    float s = 0.f, s2 = 0.f;
#pragma unroll
    for (int e = 0; e < 8; e++) { s += v[e]; s2 = fmaf(v[e], v[e], s2); }

#pragma unroll
    for (int o = 16; o > 0; o >>= 1) {
        s  += __shfl_xor_sync(0xffffffffu, s,  o);
        s2 += __shfl_xor_sync(0xffffffffu, s2, o);
    }
    __shared__ float sh[16];
    int w = tid >> 5, lane = tid & 31;
    if (lane == 0) { sh[w] = s; sh[8 + w] = s2; }
    __syncthreads();
    float S = 0.f, S2 = 0.f;
    if (lane < 8) { S = sh[lane]; S2 = sh[8 + lane]; }
#pragma unroll
    for (int o = 4; o > 0; o >>= 1) {
        S  += __shfl_xor_sync(0xffffffffu, S,  o);
        S2 += __shfl_xor_sync(0xffffffffu, S2, o);
    }
    S  = __shfl_sync(0xffffffffu, S,  0);
    S2 = __shfl_sync(0xffffffffu, S2, 0);

    const float invD = 1.f / (float)D_DIM;
    float mu = S * invD;
    float var = fmaf(S2, invD, -mu * mu);
    float inv = rsqrtf(var + LN_EPS);

    float g[8], be[8];
    *(float4*)&g[0]  = *(const float4*)&gamma[tid * 8];
    *(float4*)&g[4]  = *(const float4*)&gamma[tid * 8 + 4];
    *(float4*)&be[0] = *(const float4*)&beta[tid * 8];
    *(float4*)&be[4] = *(const float4*)&beta[tid * 8 + 4];

    float r[8];
#pragma unroll
    for (int e = 0; e < 8; e++)
        r[e] = fmaf((v[e] - mu) * inv, g[e], be[e]);

    float* orow = &out[(size_t)row * D_DIM];
    *(float4*)&orow[tid * 8]     = make_float4(r[0], r[1], r[2], r[3]);
    *(float4*)&orow[tid * 8 + 4] = make_float4(r[4], r[5], r[6], r[7]);
}

// ---------------------------------------------------------------------------
extern "C" void kernel_launch(void* const* d_in, const int* in_sizes, int n_in,
                              void* d_out, int out_size)
{
    const float* x     = (const float*)d_in[0];
    const float* W_in  = (const float*)d_in[1];
    const float* W_fwd = (const float*)d_in[2];
    const float* W_bwd = (const float*)d_in[3];
    const float* W_out = (const float*)d_in[4];
    const float* gamma = (const float*)d_in[5];
    const float* beta  = (const float*)d_in[6];
    float* out = (float*)d_out;

    float *xhi, *xlo, *zp, *zhi, *zlo, *dgp, *hp, *hhi, *hlo, *op;
    float *w1h, *w1l, *w2h, *w2l, *w3h, *w3l;
    cudaGetSymbolAddress((void**)&xhi, g_xhi);
    cudaGetSymbolAddress((void**)&xlo, g_xlo);
    cudaGetSymbolAddress((void**)&zp,  g_z);
    cudaGetSymbolAddress((void**)&zhi, g_zhi);
    cudaGetSymbolAddress((void**)&zlo, g_zlo);
    cudaGetSymbolAddress((void**)&dgp, g_dg);
    cudaGetSymbolAddress((void**)&hp,  g_h);
    cudaGetSymbolAddress((void**)&hhi, g_hhi);
    cudaGetSymbolAddress((void**)&hlo, g_hlo);
    cudaGetSymbolAddress((void**)&op,  g_out);
    cudaGetSymbolAddress((void**)&w1h, g_w1h);
    cudaGetSymbolAddress((void**)&w1l, g_w1l);
    cudaGetSymbolAddress((void**)&w2h, g_w2h);
    cudaGetSymbolAddress((void**)&w2l, g_w2l);
    cudaGetSymbolAddress((void**)&w3h, g_w3h);
    cudaGetSymbolAddress((void**)&w3l, g_w3l);

    cudaFuncSetAttribute(gemm_tc<0>, cudaFuncAttributeMaxDynamicSharedMemorySize, GSMEM);
    cudaFuncSetAttribute(gemm_tc<2>, cudaFuncAttributeMaxDynamicSharedMemorySize, GSMEM);
    cudaFuncSetAttribute(gemm_tc<3>, cudaFuncAttributeMaxDynamicSharedMemorySize, GSMEM);

    dim3 tb(32, 8);

    // input split + weight transposes (K-major hi/lo)
    split_kernel<<<2048, 256>>>(x, xhi, xlo, (size_t)M_TOTAL * D_DIM / 4);
    transpose_split<<<dim3(DI_DIM / 32, D_DIM / 32), tb>>>(W_in, w1h, w1l, D_DIM, DI_DIM);
    transpose_split<<<dim3(512 / 32, DI_DIM / 32), tb>>>(W_fwd, w2h, w2l, DI_DIM, 512);
    transpose_split<<<dim3(512 / 32, DI_DIM / 32), tb>>>(
        W_bwd, w2h + (size_t)512 * DI_DIM, w2l + (size_t)512 * DI_DIM, DI_DIM, 512);
    transpose_split<<<dim3(D_DIM / 32, 512 / 32), tb>>>(W_out, w3h, w3l, 512, D_DIM);

    // z = x @ W_in  (plain + hi/lo split epilogue)
    gemm_tc<0><<<dim3(DI_DIM / 128, M_TOTAL / 128), 128, GSMEM>>>(
        xhi, xlo, w1h, w1l, zp, zhi, zlo, nullptr, DI_DIM, D_DIM);

    // dg^T = act(z @ [W_fwd|W_bwd])^T
    gemm_tc<2><<<dim3(1024 / 128, M_TOTAL / 128), 128, GSMEM>>>(
        zhi, zlo, w2h, w2l, dgp, nullptr, nullptr, zp, 1024, DI_DIM);

    // bidirectional gated scans -> h^T
    scan_kernel<<<dim3(DI_DIM, 4, 2), 256>>>();

    // h^T -> h row-major hi/lo
    transpose_split<<<dim3(M_TOTAL / 32, 512 / 32), tb>>>(hp, hhi, hlo, 512, M_TOTAL);

    // y = h @ W_out + x
    gemm_tc<3><<<dim3(D_DIM / 128, M_TOTAL / 128), 128, GSMEM>>>(
        hhi, hlo, w3h, w3l, op, nullptr, nullptr, x, D_DIM, 512);

    // LayerNorm
    ln_kernel<<<M_TOTAL, 256>>>(gamma, beta, out);
}

// round 4
// speedup vs baseline: 2.7553x; 1.1065x over previous
#include <cuda_runtime.h>
#include <math.h>
#include <stdint.h>

#define M_TOTAL 16384
#define D_DIM   2048
#define DI_DIM  256
#define L_SEQ   4096
#define LN_EPS  1e-5f

// ---------------- scratch ----------------
__device__ float g_z  [(size_t)M_TOTAL * DI_DIM];     // z row-major
__device__ float g_dg [(size_t)1024 * M_TOTAL];       // dg^T
__device__ float g_h  [(size_t)512  * M_TOTAL];       // h^T
__device__ float g_hrm[(size_t)M_TOTAL * 512];        // h row-major
__device__ float g_out[(size_t)M_TOTAL * D_DIM];      // y = out + x
__device__ float g_wt1[(size_t)DI_DIM * D_DIM];       // W_in^T  [256][2048]
__device__ float g_wt2[(size_t)1024 * DI_DIM];        // [W_fwd|W_bwd]^T
__device__ float g_wt3[(size_t)D_DIM * 512];          // W_out^T

// ---------------- arch feature gate ----------------
#if defined(__CUDA_ARCH_FEAT_SM103_ALL) || defined(__CUDA_ARCH_FEAT_SM100_ALL) || \
    defined(__CUDA_ARCH_FEAT_SM101_ALL) || defined(__CUDA_ARCH_SPECIFIC__)
#define TC_OK 1
#else
#define TC_OK 0
#endif

// ---------------- PTX helpers ----------------
__device__ __forceinline__ uint32_t smem_u32(const void* p) {
    uint32_t a;
    asm("{ .reg .u64 t; cvta.to.shared.u64 t, %1; cvt.u32.u64 %0, t; }" : "=r"(a) : "l"(p));
    return a;
}

__device__ __forceinline__ float tf32_rnd(float a) {
    uint32_t u;
    asm("cvt.rna.tf32.f32 %0, %1;" : "=r"(u) : "f"(a));
    return __uint_as_float(u);
}

#define CP_ASYNC16(dst, src) \
    asm volatile("cp.async.cg.shared.global [%0], [%1], 16;" :: "r"(dst), "l"(src))
#define CP_COMMIT() asm volatile("cp.async.commit_group;" ::: "memory")
#define CP_WAIT1()  asm volatile("cp.async.wait_group 1;" ::: "memory")

#define MBARRIER_INIT(addr, cnt) \
    asm volatile("mbarrier.init.shared.b64 [%0], %1;" :: "r"(addr), "r"(cnt) : "memory")

__device__ __forceinline__ void mbar_wait(uint32_t mbar, uint32_t parity) {
    asm volatile(
        "{\n\t.reg .pred P;\n\t"
        "W0_%=:\n\t"
        "mbarrier.try_wait.parity.acquire.cta.shared::cta.b64 P, [%0], %1, 0x989680;\n\t"
        "@P bra W1_%=;\n\t"
        "bra W0_%=;\n\t"
        "W1_%=:\n\t}"
        :: "r"(mbar), "r"(parity) : "memory");
}

#define FENCE_ASYNC_SHARED() \
    asm volatile("fence.proxy.async.shared::cta;" ::: "memory")

#if TC_OK
#define TCGEN05_ALLOC(smem_res, ncols) \
    asm volatile("tcgen05.alloc.cta_group::1.sync.aligned.shared::cta.b32 [%0], %1;" \
                 :: "r"((uint32_t)(smem_res)), "r"((uint32_t)(ncols)) : "memory")
#define TCGEN05_DEALLOC(tmem, ncols) \
    asm volatile("tcgen05.dealloc.cta_group::1.sync.aligned.b32 %0, %1;" \
                 :: "r"(tmem), "r"((uint32_t)(ncols)))
#define TCGEN05_RELINQUISH() \
    asm volatile("tcgen05.relinquish_alloc_permit.cta_group::1.sync.aligned;")
#define TCGEN05_COMMIT(mbar) \
    asm volatile("tcgen05.commit.cta_group::1.mbarrier::arrive::one.shared::cluster.b64 [%0];" \
                 :: "r"((uint32_t)(mbar)) : "memory")
#define TCGEN05_FENCE_AFTER() \
    asm volatile("tcgen05.fence::after_thread_sync;" ::: "memory")
#define TCGEN05_WAIT_LD() \
    asm volatile("tcgen05.wait::ld.sync.aligned;" ::: "memory")

#define TCGEN05_LD_X32(r, tmem_addr) \
    asm volatile( \
        "tcgen05.ld.sync.aligned.32x32b.x32.b32 " \
        "{%0, %1, %2, %3, %4, %5, %6, %7, " \
        " %8, %9, %10, %11, %12, %13, %14, %15, " \
        " %16, %17, %18, %19, %20, %21, %22, %23, " \
        " %24, %25, %26, %27, %28, %29, %30, %31}, [%32];" \
        : "=r"((r)[0]),  "=r"((r)[1]),  "=r"((r)[2]),  "=r"((r)[3]), \
          "=r"((r)[4]),  "=r"((r)[5]),  "=r"((r)[6]),  "=r"((r)[7]), \
          "=r"((r)[8]),  "=r"((r)[9]),  "=r"((r)[10]), "=r"((r)[11]), \
          "=r"((r)[12]), "=r"((r)[13]), "=r"((r)[14]), "=r"((r)[15]), \
          "=r"((r)[16]), "=r"((r)[17]), "=r"((r)[18]), "=r"((r)[19]), \
          "=r"((r)[20]), "=r"((r)[21]), "=r"((r)[22]), "=r"((r)[23]), \
          "=r"((r)[24]), "=r"((r)[25]), "=r"((r)[26]), "=r"((r)[27]), \
          "=r"((r)[28]), "=r"((r)[29]), "=r"((r)[30]), "=r"((r)[31]) \
        : "r"(tmem_addr))

__device__ __forceinline__ void mma_tf32(uint32_t d, uint64_t ad, uint64_t bd,
                                         uint32_t idesc, uint32_t en) {
    asm volatile(
        "{\n\t.reg .pred p;\n\t"
        "setp.ne.u32 p, %5, 0;\n\t"
        "tcgen05.mma.cta_group::1.kind::tf32 [%0], %1, %2, %3, {%4, %4, %4, %4}, p;\n\t}"
        :: "r"(d), "l"(ad), "l"(bd), "r"(idesc), "r"(0u), "r"(en) : "memory");
}
#else
#define TCGEN05_ALLOC(smem_res, ncols)  do {} while (0)
#define TCGEN05_DEALLOC(tmem, ncols)    do {} while (0)
#define TCGEN05_RELINQUISH()            do {} while (0)
#define TCGEN05_COMMIT(mbar)            do {} while (0)
#define TCGEN05_FENCE_AFTER()           do {} while (0)
#define TCGEN05_WAIT_LD()               do {} while (0)
#define TCGEN05_LD_X32(r, tmem_addr) \
    do { _Pragma("unroll") for (int _i = 0; _i < 32; _i++) (r)[_i] = 0u; } while (0)
__device__ __forceinline__ void mma_tf32(uint32_t, uint64_t, uint64_t, uint32_t, uint32_t) {}
#endif

// SW128 K-major SMEM descriptor (layout=2, ver=1, SBO=64, LBO=1)
__device__ __forceinline__ uint64_t sdesc(uint32_t addr) {
    return 0x4000404000010000ULL | (uint64_t)((addr >> 4) & 0x3FFF);
}

// ---------------- SMEM layout ----------------
// stage: [Ahi 16K | Alo 16K | Bhi BN*128 | Blo BN*128], 2 stages
#define STG_OFF 1024
#define GSMEM_FOR(BN) (STG_OFF + 2 * (32768 + 2 * (BN) * 128))

// ---------------------------------------------------------------------------
// tcgen05 tf32 GEMM, single pass over K, 3 emulation MMAs per 32-K chunk.
// A (fp32) and B (fp32, K-major) are split to tf32 hi/lo IN-KERNEL.
// C[M,N] = A[M,K] * Bt[N,K]^T. Tile 128 x BN. 256 threads.
// MODE 0: row-major store
// MODE 2: delta/gate epilogue, transposed store into dg^T (EX = z row-major)
// MODE 3: row-major store + residual EX
// ---------------------------------------------------------------------------
template<int MODE, int BN>
__global__ void __launch_bounds__(256)
gemm_tc(const float* __restrict__ A, const float* __restrict__ Bt,
        float* __restrict__ C, const float* __restrict__ EX, int N, int K)
{
    extern __shared__ __align__(1024) char dsm[];
    uint32_t sb = smem_u32(dsm);
    constexpr int BNB   = BN * 128;
    constexpr int STAGE = 32768 + 2 * BNB;
    constexpr uint32_t IDESC =
        (1u << 4) | (2u << 7) | (2u << 10) | ((uint32_t)(BN / 8) << 17) | (8u << 24);

    int tid = threadIdx.x, wid = tid >> 5, lane = tid & 31;
    int n0 = blockIdx.x * BN, m0 = blockIdx.y * 128;

    if (wid == 0) TCGEN05_ALLOC(sb, BN);
    if (tid == 0) { MBARRIER_INIT(sb + 16, 1); MBARRIER_INIT(sb + 24, 1); }
    __syncthreads();
    uint32_t tmem;
    asm volatile("ld.shared.b32 %0, [%1];" : "=r"(tmem) : "r"(sb));
    if (wid == 0) TCGEN05_RELINQUISH();

    const int NC = K >> 5;           // 32-float K chunks (NC >= 2 for all uses)
    const int k4 = tid & 7;          // 16B word within 128B row
    const int rb = tid >> 3;         // row 0..31

    auto load_tiles = [&](int c, int stage) {
        int kc = c * 32;
        uint32_t sa = sb + STG_OFF + stage * STAGE;
#pragma unroll
        for (int i = 0; i < 4; i++) {                 // A raw: 128 rows
            int r = rb + 32 * i;
            uint32_t byte = r * 128 + k4 * 16;
            uint32_t sw = byte ^ ((byte >> 3) & 0x70);
            CP_ASYNC16(sa + sw, (const void*)(A + (size_t)(m0 + r) * K + kc + k4 * 4));
        }
#pragma unroll
        for (int i = 0; i < BN / 32; i++) {           // B raw: BN rows
            int r = rb + 32 * i;
            uint32_t byte = r * 128 + k4 * 16;
            uint32_t sw = byte ^ ((byte >> 3) & 0x70);
            CP_ASYNC16(sa + 32768 + sw, (const void*)(Bt + (size_t)(n0 + r) * K + kc + k4 * 4));
        }
        CP_COMMIT();
    };

    // in-SMEM tf32 split: hi overwrites raw, lo to side buffer
    auto convert = [&](int stage) {
        char* base = dsm + STG_OFF + (size_t)stage * STAGE;
        float4* ar = (float4*)base;
        float4* al = (float4*)(base + 16384);
#pragma unroll
        for (int i = 0; i < 4; i++) {                 // 16KB A
            int idx = tid + i * 256;
            float4 v = ar[idx];
            float4 h = make_float4(tf32_rnd(v.x), tf32_rnd(v.y), tf32_rnd(v.z), tf32_rnd(v.w));
            ar[idx] = h;
            al[idx] = make_float4(v.x - h.x, v.y - h.y, v.z - h.z, v.w - h.w);
        }
        float4* br = (float4*)(base + 32768);
        float4* bl = (float4*)(base + 32768 + BNB);
#pragma unroll
        for (int i = 0; i < BNB / 4096; i++) {        // BN*128 bytes B
            int idx = tid + i * 256;
            float4 v = br[idx];
            float4 h = make_float4(tf32_rnd(v.x), tf32_rnd(v.y), tf32_rnd(v.z), tf32_rnd(v.w));
            br[idx] = h;
            bl[idx] = make_float4(v.x - h.x, v.y - h.y, v.z - h.z, v.w - h.w);
        }
    };

    load_tiles(0, 0);
    load_tiles(1, 1);

    for (int c = 0; c < NC; c++) {
        int st = c & 1;
        CP_WAIT1();                 // chunk c's stage resident (1 commit/iter invariant)
        __syncthreads();
        convert(st);
        FENCE_ASYNC_SHARED();
        __syncthreads();
        if (tid == 0) {
            uint32_t sa = sb + STG_OFF + st * STAGE;
            uint64_t ah = sdesc(sa);
            uint64_t al = sdesc(sa + 16384);
            uint64_t bh = sdesc(sa + 32768);
            uint64_t bl = sdesc(sa + 32768 + BNB);
#pragma unroll
            for (int j = 0; j < 4; j++)
                mma_tf32(tmem, ah + 2 * j, bh + 2 * j, IDESC, (uint32_t)((c | j) != 0));
#pragma unroll
            for (int j = 0; j < 4; j++)
                mma_tf32(tmem, ah + 2 * j, bl + 2 * j, IDESC, 1u);
#pragma unroll
            for (int j = 0; j < 4; j++)
                mma_tf32(tmem, al + 2 * j, bh + 2 * j, IDESC, 1u);
            TCGEN05_COMMIT(sb + 16 + 8 * st);
        }
        if (c + 2 < NC) {
            mbar_wait(sb + 16 + 8 * st, (uint32_t)((c >> 1) & 1));
            load_tiles(c + 2, st);
        } else {
            CP_COMMIT();            // empty group keeps wait accounting exact
        }
    }
    mbar_wait(sb + 16 + 8 * ((NC - 1) & 1), (uint32_t)(((NC - 1) >> 1) & 1));
    TCGEN05_FENCE_AFTER();

    // -------- epilogue: 8 warps; warp w -> rows (w&3)*32, col half (w>>2) ----
    int m = m0 + (wid & 3) * 32 + lane;
    int ccb = (wid >> 2) * (BN / 2);
    uint32_t regs[32];
#pragma unroll
    for (int ccq = 0; ccq < BN / 2; ccq += 32) {
        int cc = ccb + ccq;
        TCGEN05_LD_X32(regs, tmem + cc);
        TCGEN05_WAIT_LD();

        if (MODE == 0 || MODE == 3) {
#pragma unroll
            for (int j = 0; j < 32; j += 4) {
                size_t off = (size_t)m * N + n0 + cc + j;
                float4 v = make_float4(__uint_as_float(regs[j]),
                                       __uint_as_float(regs[j + 1]),
                                       __uint_as_float(regs[j + 2]),
                                       __uint_as_float(regs[j + 3]));
                if (MODE == 3) {
                    float4 r4 = *(const float4*)&EX[off];
                    v.x += r4.x; v.y += r4.y; v.z += r4.z; v.w += r4.w;
                }
                *(float4*)&C[off] = v;
            }
        } else {  // MODE 2: delta/gate, transposed store into dg^T
            int jj0 = (n0 + cc) & 511;
            if (jj0 < 256) {
#pragma unroll
                for (int j = 0; j < 32; j++) {
                    float v = __uint_as_float(regs[j]);
                    v = 1.f / (1.f + expf(-v));
                    C[(size_t)(n0 + cc + j) * M_TOTAL + m] = v;
                }
            } else {
                int ch0 = jj0 - 256;
#pragma unroll
                for (int j = 0; j < 32; j += 4) {
                    float4 zv = *(const float4*)&EX[(size_t)m * DI_DIM + ch0 + j];
                    C[(size_t)(n0 + cc + j + 0) * M_TOTAL + m] = __uint_as_float(regs[j + 0]) * zv.x;
                    C[(size_t)(n0 + cc + j + 1) * M_TOTAL + m] = __uint_as_float(regs[j + 1]) * zv.y;
                    C[(size_t)(n0 + cc + j + 2) * M_TOTAL + m] = __uint_as_float(regs[j + 2]) * zv.z;
                    C[(size_t)(n0 + cc + j + 3) * M_TOTAL + m] = __uint_as_float(regs[j + 3]) * zv.w;
                }
            }
        }
    }

    __syncthreads();
    if (wid == 0) TCGEN05_DEALLOC(tmem, BN);
}

// ---------------------------------------------------------------------------
// 32x32 tiled transpose: in[R][C] -> out[C][R]
// ---------------------------------------------------------------------------
__global__ void __launch_bounds__(256)
transpose_plain(const float* __restrict__ in, float* __restrict__ out, int R, int C)
{
    __shared__ float t[32][33];
    int c0 = blockIdx.x * 32, r0 = blockIdx.y * 32;
    int tx = threadIdx.x, ty = threadIdx.y;
#pragma unroll
    for (int i = 0; i < 32; i += 8)
        t[ty + i][tx] = in[(size_t)(r0 + ty + i) * C + c0 + tx];
    __syncthreads();
#pragma unroll
    for (int i = 0; i < 32; i += 8)
        out[(size_t)(c0 + ty + i) * R + r0 + tx] = t[tx][ty + i];
}

// ---------------------------------------------------------------------------
// Gated linear scan: block per (channel, batch, dir)
// ---------------------------------------------------------------------------
__global__ __launch_bounds__(256)
void scan_kernel()
{
    int d = blockIdx.x, bb = blockIdx.y, dir = blockIdx.z;
    const float* dptr = &g_dg[(size_t)(dir * 512 + d)       * M_TOTAL + bb * L_SEQ];
    const float* gptr = &g_dg[(size_t)(dir * 512 + 256 + d) * M_TOTAL + bb * L_SEQ];
    float*       hptr = &g_h [(size_t)(dir * 256 + d)       * M_TOTAL + bb * L_SEQ];

    int tid = threadIdx.x;
    int base = (dir == 0) ? tid * 16 : (L_SEQ - 16 * (tid + 1));

    float tmpd[16], tmpg[16];
#pragma unroll
    for (int q = 0; q < 4; q++) {
        *(float4*)&tmpd[q * 4] = *(const float4*)&dptr[base + q * 4];
        *(float4*)&tmpg[q * 4] = *(const float4*)&gptr[base + q * 4];
    }
    float dl[16], gt[16];
#pragma unroll
    for (int e = 0; e < 16; e++) {
        int src = (dir == 0) ? e : (15 - e);
        dl[e] = tmpd[src];
        gt[e] = tmpg[src];
    }

    float Aseg = 1.f, Bseg = 0.f;
#pragma unroll
    for (int e = 0; e < 16; e++) {
        Aseg = Aseg * dl[e];
        Bseg = fmaf(Bseg, dl[e], gt[e]);
    }

    __shared__ float sA[256], sB[256];
    sA[tid] = Aseg; sB[tid] = Bseg;
    __syncthreads();
#pragma unroll
    for (int off = 1; off < 256; off <<= 1) {
        float pA = 0.f, pB = 0.f;
        bool has = (tid >= off);
        if (has) { pA = sA[tid - off]; pB = sB[tid - off]; }
        __syncthreads();
        if (has) {
            float Ac = sA[tid], Bc = sB[tid];
            sA[tid] = Ac * pA;
            sB[tid] = fmaf(Ac, pB, Bc);
        }
        __syncthreads();
    }

    float h = (tid == 0) ? 0.f : sB[tid - 1];
    float hv[16];
#pragma unroll
    for (int e = 0; e < 16; e++) {
        h = fmaf(h, dl[e], gt[e]);
        hv[e] = h;
    }

    float outv[16];
#pragma unroll
    for (int q = 0; q < 16; q++)
        outv[q] = (dir == 0) ? hv[q] : hv[15 - q];
#pragma unroll
    for (int q = 0; q < 4; q++)
        *(float4*)&hptr[base + q * 4] =
            make_float4(outv[q * 4], outv[q * 4 + 1], outv[q * 4 + 2], outv[q * 4 + 3]);
}

// ---------------------------------------------------------------------------
// LayerNorm over D=2048 per row
// ---------------------------------------------------------------------------
__global__ __launch_bounds__(256)
void ln_kernel(const float* __restrict__ gamma, const float* __restrict__ beta,
               float* __restrict__ out)
{
    int row = blockIdx.x;
    int tid = threadIdx.x;
    const float* yrow = &g_out[(size_t)row * D_DIM];

    float v[8];
    *(float4*)&v[0] = *(const float4*)&yrow[tid * 8];
    *(float4*)&v[4] = *(const float4*)&yrow[tid * 8 + 4];

    float s = 0.f, s2 = 0.f;
#pragma unroll
    for (int e = 0; e < 8; e++) { s += v[e]; s2 = fmaf(v[e], v[e], s2); }

#pragma unroll
    for (int o = 16; o > 0; o >>= 1) {
        s  += __shfl_xor_sync(0xffffffffu, s,  o);
        s2 += __shfl_xor_sync(0xffffffffu, s2, o);
    }
    __shared__ float sh[16];
    int w = tid >> 5, lane = tid & 31;
    if (lane == 0) { sh[w] = s; sh[8 + w] = s2; }
    __syncthreads();
    float S = 0.f, S2 = 0.f;
    if (lane < 8) { S = sh[lane]; S2 = sh[8 + lane]; }
#pragma unroll
    for (int o = 4; o > 0; o >>= 1) {
        S  += __shfl_xor_sync(0xffffffffu, S,  o);
        S2 += __shfl_xor_sync(0xffffffffu, S2, o);
    }
    S  = __shfl_sync(0xffffffffu, S,  0);
    S2 = __shfl_sync(0xffffffffu, S2, 0);

    const float invD = 1.f / (float)D_DIM;
    float mu = S * invD;
    float var = fmaf(S2, invD, -mu * mu);
    float inv = rsqrtf(var + LN_EPS);

    float g[8], be[8];
    *(float4*)&g[0]  = *(const float4*)&gamma[tid * 8];
    *(float4*)&g[4]  = *(const float4*)&gamma[tid * 8 + 4];
    *(float4*)&be[0] = *(const float4*)&beta[tid * 8];
    *(float4*)&be[4] = *(const float4*)&beta[tid * 8 + 4];

    float r[8];
#pragma unroll
    for (int e = 0; e < 8; e++)
        r[e] = fmaf((v[e] - mu) * inv, g[e], be[e]);

    float* orow = &out[(size_t)row * D_DIM];
    *(float4*)&orow[tid * 8]     = make_float4(r[0], r[1], r[2], r[3]);
    *(float4*)&orow[tid * 8 + 4] = make_float4(r[4], r[5], r[6], r[7]);
}

// ---------------------------------------------------------------------------
extern "C" void kernel_launch(void* const* d_in, const int* in_sizes, int n_in,
                              void* d_out, int out_size)
{
    const float* x     = (const float*)d_in[0];
    const float* W_in  = (const float*)d_in[1];
    const float* W_fwd = (const float*)d_in[2];
    const float* W_bwd = (const float*)d_in[3];
    const float* W_out = (const float*)d_in[4];
    const float* gamma = (const float*)d_in[5];
    const float* beta  = (const float*)d_in[6];
    float* out = (float*)d_out;

    float *zp, *dgp, *hp, *hrmp, *op, *wt1, *wt2, *wt3;
    cudaGetSymbolAddress((void**)&zp,   g_z);
    cudaGetSymbolAddress((void**)&dgp,  g_dg);
    cudaGetSymbolAddress((void**)&hp,   g_h);
    cudaGetSymbolAddress((void**)&hrmp, g_hrm);
    cudaGetSymbolAddress((void**)&op,   g_out);
    cudaGetSymbolAddress((void**)&wt1,  g_wt1);
    cudaGetSymbolAddress((void**)&wt2,  g_wt2);
    cudaGetSymbolAddress((void**)&wt3,  g_wt3);

    const int GSMEM = GSMEM_FOR(256);
    cudaFuncSetAttribute(gemm_tc<0, 256>, cudaFuncAttributeMaxDynamicSharedMemorySize, GSMEM);
    cudaFuncSetAttribute(gemm_tc<2, 256>, cudaFuncAttributeMaxDynamicSharedMemorySize, GSMEM);
    cudaFuncSetAttribute(gemm_tc<3, 256>, cudaFuncAttributeMaxDynamicSharedMemorySize, GSMEM);

    dim3 tb(32, 8);

    // weight transposes -> plain K-major B operands
    transpose_plain<<<dim3(DI_DIM / 32, D_DIM / 32), tb>>>(W_in, wt1, D_DIM, DI_DIM);
    transpose_plain<<<dim3(512 / 32, DI_DIM / 32), tb>>>(W_fwd, wt2, DI_DIM, 512);
    transpose_plain<<<dim3(512 / 32, DI_DIM / 32), tb>>>(
        W_bwd, wt2 + (size_t)512 * DI_DIM, DI_DIM, 512);
    transpose_plain<<<dim3(D_DIM / 32, 512 / 32), tb>>>(W_out, wt3, 512, D_DIM);

    // z = x @ W_in   [M,256] (single N-tile column)
    gemm_tc<0, 256><<<dim3(1, M_TOTAL / 128), 256, GSMEM>>>(
        x, wt1, zp, nullptr, DI_DIM, D_DIM);

    // dg^T = act(z @ [W_fwd|W_bwd])^T
    gemm_tc<2, 256><<<dim3(4, M_TOTAL / 128), 256, GSMEM>>>(
        zp, wt2, dgp, zp, 1024, DI_DIM);

    // bidirectional gated scans -> h^T
    scan_kernel<<<dim3(DI_DIM, 4, 2), 256>>>();

    // h^T -> h row-major
    transpose_plain<<<dim3(M_TOTAL / 32, 512 / 32), tb>>>(hp, hrmp, 512, M_TOTAL);

    // y = h @ W_out + x
    gemm_tc<3, 256><<<dim3(8, M_TOTAL / 128), 256, GSMEM>>>(
        hrmp, wt3, op, x, D_DIM, 512);

    // LayerNorm
    ln_kernel<<<M_TOTAL, 256>>>(gamma, beta, out);
}

// round 5
// speedup vs baseline: 3.9301x; 1.4264x over previous
#include <cuda_runtime.h>
#include <cuda_bf16.h>
#include <math.h>
#include <stdint.h>

#define M_TOTAL 16384
#define D_DIM   2048
#define DI_DIM  256
#define L_SEQ   4096
#define LN_EPS  1e-5f

// ---------------- scratch ----------------
__device__ float g_z  [(size_t)M_TOTAL * DI_DIM];     // z fp32 row-major (gating)
__device__ float g_dg [(size_t)1024 * M_TOTAL];       // dg^T
__device__ float g_h  [(size_t)512  * M_TOTAL];       // h^T fp32
__device__ float g_out[(size_t)M_TOTAL * D_DIM];      // y = out + x

__device__ __nv_bfloat16 g_xh [(size_t)M_TOTAL * D_DIM];
__device__ __nv_bfloat16 g_xl [(size_t)M_TOTAL * D_DIM];
__device__ __nv_bfloat16 g_zh [(size_t)M_TOTAL * DI_DIM];
__device__ __nv_bfloat16 g_zl [(size_t)M_TOTAL * DI_DIM];
__device__ __nv_bfloat16 g_hh [(size_t)M_TOTAL * 512];
__device__ __nv_bfloat16 g_hl [(size_t)M_TOTAL * 512];
__device__ __nv_bfloat16 g_w1h[(size_t)DI_DIM * D_DIM];
__device__ __nv_bfloat16 g_w1l[(size_t)DI_DIM * D_DIM];
__device__ __nv_bfloat16 g_w2h[(size_t)1024 * DI_DIM];
__device__ __nv_bfloat16 g_w2l[(size_t)1024 * DI_DIM];
__device__ __nv_bfloat16 g_w3h[(size_t)D_DIM * 512];
__device__ __nv_bfloat16 g_w3l[(size_t)D_DIM * 512];

// ---------------- arch feature gate ----------------
#if defined(__CUDA_ARCH_FEAT_SM103_ALL) || defined(__CUDA_ARCH_FEAT_SM100_ALL) || \
    defined(__CUDA_ARCH_FEAT_SM101_ALL) || defined(__CUDA_ARCH_SPECIFIC__)
#define TC_OK 1
#else
#define TC_OK 0
#endif

// ---------------- helpers ----------------
__device__ __forceinline__ uint32_t smem_u32(const void* p) {
    uint32_t a;
    asm("{ .reg .u64 t; cvta.to.shared.u64 t, %1; cvt.u32.u64 %0, t; }" : "=r"(a) : "l"(p));
    return a;
}

__device__ __forceinline__ float bf16hi(float a) {
    return __bfloat162float(__float2bfloat16_rn(a));
}
__device__ __forceinline__ uint32_t bf16pack(float a, float b) {
    __nv_bfloat162 t = __floats2bfloat162_rn(a, b);
    return *reinterpret_cast<uint32_t*>(&t);
}

#define CP_ASYNC16(dst, src) \
    asm volatile("cp.async.cg.shared.global [%0], [%1], 16;" :: "r"(dst), "l"(src))
#define CP_COMMIT() asm volatile("cp.async.commit_group;" ::: "memory")
#define CP_WAIT1()  asm volatile("cp.async.wait_group 1;" ::: "memory")

#define MBARRIER_INIT(addr, cnt) \
    asm volatile("mbarrier.init.shared.b64 [%0], %1;" :: "r"(addr), "r"(cnt) : "memory")

__device__ __forceinline__ void mbar_wait(uint32_t mbar, uint32_t parity) {
    asm volatile(
        "{\n\t.reg .pred P;\n\t"
        "W0_%=:\n\t"
        "mbarrier.try_wait.parity.acquire.cta.shared::cta.b64 P, [%0], %1, 0x989680;\n\t"
        "@P bra W1_%=;\n\t"
        "bra W0_%=;\n\t"
        "W1_%=:\n\t}"
        :: "r"(mbar), "r"(parity) : "memory");
}

#define FENCE_ASYNC_SHARED() \
    asm volatile("fence.proxy.async.shared::cta;" ::: "memory")

#if TC_OK
#define TCGEN05_ALLOC(smem_res, ncols) \
    asm volatile("tcgen05.alloc.cta_group::1.sync.aligned.shared::cta.b32 [%0], %1;" \
                 :: "r"((uint32_t)(smem_res)), "r"((uint32_t)(ncols)) : "memory")
#define TCGEN05_DEALLOC(tmem, ncols) \
    asm volatile("tcgen05.dealloc.cta_group::1.sync.aligned.b32 %0, %1;" \
                 :: "r"(tmem), "r"((uint32_t)(ncols)))
#define TCGEN05_RELINQUISH() \
    asm volatile("tcgen05.relinquish_alloc_permit.cta_group::1.sync.aligned;")
#define TCGEN05_COMMIT(mbar) \
    asm volatile("tcgen05.commit.cta_group::1.mbarrier::arrive::one.shared::cluster.b64 [%0];" \
                 :: "r"((uint32_t)(mbar)) : "memory")
#define TCGEN05_FENCE_AFTER() \
    asm volatile("tcgen05.fence::after_thread_sync;" ::: "memory")
#define TCGEN05_WAIT_LD() \
    asm volatile("tcgen05.wait::ld.sync.aligned;" ::: "memory")

#define TCGEN05_LD_X32(r, tmem_addr) \
    asm volatile( \
        "tcgen05.ld.sync.aligned.32x32b.x32.b32 " \
        "{%0, %1, %2, %3, %4, %5, %6, %7, " \
        " %8, %9, %10, %11, %12, %13, %14, %15, " \
        " %16, %17, %18, %19, %20, %21, %22, %23, " \
        " %24, %25, %26, %27, %28, %29, %30, %31}, [%32];" \
        : "=r"((r)[0]),  "=r"((r)[1]),  "=r"((r)[2]),  "=r"((r)[3]), \
          "=r"((r)[4]),  "=r"((r)[5]),  "=r"((r)[6]),  "=r"((r)[7]), \
          "=r"((r)[8]),  "=r"((r)[9]),  "=r"((r)[10]), "=r"((r)[11]), \
          "=r"((r)[12]), "=r"((r)[13]), "=r"((r)[14]), "=r"((r)[15]), \
          "=r"((r)[16]), "=r"((r)[17]), "=r"((r)[18]), "=r"((r)[19]), \
          "=r"((r)[20]), "=r"((r)[21]), "=r"((r)[22]), "=r"((r)[23]), \
          "=r"((r)[24]), "=r"((r)[25]), "=r"((r)[26]), "=r"((r)[27]), \
          "=r"((r)[28]), "=r"((r)[29]), "=r"((r)[30]), "=r"((r)[31]) \
        : "r"(tmem_addr))

__device__ __forceinline__ void mma_bf16(uint32_t d, uint64_t ad, uint64_t bd,
                                         uint32_t idesc, uint32_t en) {
    asm volatile(
        "{\n\t.reg .pred p;\n\t"
        "setp.ne.u32 p, %5, 0;\n\t"
        "tcgen05.mma.cta_group::1.kind::f16 [%0], %1, %2, %3, {%4, %4, %4, %4}, p;\n\t}"
        :: "r"(d), "l"(ad), "l"(bd), "r"(idesc), "r"(0u), "r"(en) : "memory");
}
#else
#define TCGEN05_ALLOC(smem_res, ncols)  do {} while (0)
#define TCGEN05_DEALLOC(tmem, ncols)    do {} while (0)
#define TCGEN05_RELINQUISH()            do {} while (0)
#define TCGEN05_COMMIT(mbar)            do {} while (0)
#define TCGEN05_FENCE_AFTER()           do {} while (0)
#define TCGEN05_WAIT_LD()               do {} while (0)
#define TCGEN05_LD_X32(r, tmem_addr) \
    do { _Pragma("unroll") for (int _i = 0; _i < 32; _i++) (r)[_i] = 0u; } while (0)
__device__ __forceinline__ void mma_bf16(uint32_t, uint64_t, uint64_t, uint32_t, uint32_t) {}
#endif

// SW128 K-major SMEM descriptor (layout=2, ver=1, SBO=64, LBO=1)
__device__ __forceinline__ uint64_t sdesc(uint32_t addr) {
    return 0x4000404000010000ULL | (uint64_t)((addr >> 4) & 0x3FFF);
}

// ---------------- SMEM layout ----------------
// stage (BK=64 bf16, BN=256): Ahi 16K @0 | Alo 16K @16K | Bhi 32K @32K | Blo 32K @64K
#define STG_OFF  1024
#define STAGE_SZ 98304
#define GSMEM    (STG_OFF + 2 * STAGE_SZ)

// idesc kind::f16 bf16: dtype=F32(1@4), atype=BF16(1@7), btype=BF16(1@10), N/8@17, M/16@24
#define IDESC_BF16 ((1u << 4) | (1u << 7) | (1u << 10) | ((256u / 8) << 17) | ((128u / 16) << 24))

// ---------------------------------------------------------------------------
// bf16x3 Ootomo GEMM: C[M,N] = A*B^T, A/B pre-split to bf16 hi/lo (K-major B).
// Tile 128x256, BK=64 bf16 per chunk, 3 MMAs per K-step (hi*hi + hi*lo + lo*hi).
// MODE 0: row-major fp32 store + bf16 hi/lo split store (z producer)
// MODE 2: delta/gate epilogue, transposed store into dg^T (EX = z fp32)
// MODE 3: row-major store + residual EX
// ---------------------------------------------------------------------------
template<int MODE>
__global__ void __launch_bounds__(256)
gemm_bf16x3(const __nv_bfloat16* __restrict__ Ah, const __nv_bfloat16* __restrict__ Al,
            const __nv_bfloat16* __restrict__ Bh, const __nv_bfloat16* __restrict__ Bl,
            float* __restrict__ C, __nv_bfloat16* __restrict__ Chi,
            __nv_bfloat16* __restrict__ Clo, const float* __restrict__ EX,
            int N, int K)
{
    extern __shared__ __align__(1024) char dsm[];
    uint32_t sb = smem_u32(dsm);
    int tid = threadIdx.x, wid = tid >> 5, lane = tid & 31;
    int n0 = blockIdx.x * 256, m0 = blockIdx.y * 128;

    if (wid == 0) TCGEN05_ALLOC(sb, 256);
    if (tid == 0) { MBARRIER_INIT(sb + 16, 1); MBARRIER_INIT(sb + 24, 1); }
    __syncthreads();
    uint32_t tmem;
    asm volatile("ld.shared.b32 %0, [%1];" : "=r"(tmem) : "r"(sb));
    if (wid == 0) TCGEN05_RELINQUISH();

    const int NC = K >> 6;           // 64-element bf16 K chunks (NC >= 2 everywhere)
    const int k4 = tid & 7;          // 16B segment (8 bf16) within 128B row
    const int rb = tid >> 3;         // row 0..31

    auto load_tiles = [&](int c, int stage) {
        int kc = c * 64;
        uint32_t sa = sb + STG_OFF + stage * STAGE_SZ;
#pragma unroll
        for (int i = 0; i < 4; i++) {                  // A: 128 rows
            int r = rb + 32 * i;
            uint32_t byte = r * 128 + k4 * 16;
            uint32_t sw = byte ^ ((byte >> 3) & 0x70);
            size_t go = (size_t)(m0 + r) * K + kc + k4 * 8;
            CP_ASYNC16(sa + sw,         (const void*)(Ah + go));
            CP_ASYNC16(sa + 16384 + sw, (const void*)(Al + go));
        }
#pragma unroll
        for (int i = 0; i < 8; i++) {                  // B: 256 rows
            int r = rb + 32 * i;
            uint32_t byte = r * 128 + k4 * 16;
            uint32_t sw = byte ^ ((byte >> 3) & 0x70);
            size_t go = (size_t)(n0 + r) * K + kc + k4 * 8;
            CP_ASYNC16(sa + 32768 + sw, (const void*)(Bh + go));
            CP_ASYNC16(sa + 65536 + sw, (const void*)(Bl + go));
        }
        CP_COMMIT();
    };

    load_tiles(0, 0);
    load_tiles(1, 1);

    for (int c = 0; c < NC; c++) {
        int st = c & 1;
        CP_WAIT1();                 // chunk c resident (1 commit/iter invariant)
        FENCE_ASYNC_SHARED();
        __syncthreads();
        if (tid == 0) {
            uint32_t sa = sb + STG_OFF + st * STAGE_SZ;
            uint64_t ah = sdesc(sa);
            uint64_t al = sdesc(sa + 16384);
            uint64_t bh = sdesc(sa + 32768);
            uint64_t bl = sdesc(sa + 65536);
#pragma unroll
            for (int j = 0; j < 4; j++)                 // K=16 per step: +32B = +2 units
                mma_bf16(tmem, ah + 2 * j, bh + 2 * j, IDESC_BF16, (uint32_t)((c | j) != 0));
#pragma unroll
            for (int j = 0; j < 4; j++)
                mma_bf16(tmem, ah + 2 * j, bl + 2 * j, IDESC_BF16, 1u);
#pragma unroll
            for (int j = 0; j < 4; j++)
                mma_bf16(tmem, al + 2 * j, bh + 2 * j, IDESC_BF16, 1u);
            TCGEN05_COMMIT(sb + 16 + 8 * st);
        }
        if (c + 2 < NC) {
            mbar_wait(sb + 16 + 8 * st, (uint32_t)((c >> 1) & 1));
            load_tiles(c + 2, st);
        } else {
            CP_COMMIT();            // empty group keeps wait accounting exact
        }
    }
    mbar_wait(sb + 16 + 8 * ((NC - 1) & 1), (uint32_t)(((NC - 1) >> 1) & 1));
    TCGEN05_FENCE_AFTER();

    // -------- epilogue: warp w -> rows (w&3)*32, col half (w>>2)*128 --------
    int m = m0 + (wid & 3) * 32 + lane;
    int ccb = (wid >> 2) * 128;
    uint32_t regs[32];
#pragma unroll
    for (int ccq = 0; ccq < 128; ccq += 32) {
        int cc = ccb + ccq;
        TCGEN05_LD_X32(regs, tmem + cc);
        TCGEN05_WAIT_LD();

        if (MODE == 0) {
#pragma unroll
            for (int j = 0; j < 32; j += 4) {
                size_t off = (size_t)m * N + n0 + cc + j;
                float4 v = make_float4(__uint_as_float(regs[j]),
                                       __uint_as_float(regs[j + 1]),
                                       __uint_as_float(regs[j + 2]),
                                       __uint_as_float(regs[j + 3]));
                *(float4*)&C[off] = v;
                float hx = bf16hi(v.x), hy = bf16hi(v.y), hz = bf16hi(v.z), hw = bf16hi(v.w);
                uint2 hh = make_uint2(bf16pack(v.x, v.y), bf16pack(v.z, v.w));
                uint2 ll = make_uint2(bf16pack(v.x - hx, v.y - hy),
                                      bf16pack(v.z - hz, v.w - hw));
                *(uint2*)&Chi[off] = hh;
                *(uint2*)&Clo[off] = ll;
            }
        } else if (MODE == 3) {
#pragma unroll
            for (int j = 0; j < 32; j += 4) {
                size_t off = (size_t)m * N + n0 + cc + j;
                float4 v = make_float4(__uint_as_float(regs[j]),
                                       __uint_as_float(regs[j + 1]),
                                       __uint_as_float(regs[j + 2]),
                                       __uint_as_float(regs[j + 3]));
                float4 r4 = *(const float4*)&EX[off];
                v.x += r4.x; v.y += r4.y; v.z += r4.z; v.w += r4.w;
                *(float4*)&C[off] = v;
            }
        } else {  // MODE 2: delta/gate, transposed store into dg^T
            int jj0 = (n0 + cc) & 511;
            if (jj0 < 256) {
#pragma unroll
                for (int j = 0; j < 32; j++) {
                    float v = __uint_as_float(regs[j]);
                    v = 1.f / (1.f + expf(-v));
                    C[(size_t)(n0 + cc + j) * M_TOTAL + m] = v;
                }
            } else {
                int ch0 = jj0 - 256;
#pragma unroll
                for (int j = 0; j < 32; j += 4) {
                    float4 zv = *(const float4*)&EX[(size_t)m * DI_DIM + ch0 + j];
                    C[(size_t)(n0 + cc + j + 0) * M_TOTAL + m] = __uint_as_float(regs[j + 0]) * zv.x;
                    C[(size_t)(n0 + cc + j + 1) * M_TOTAL + m] = __uint_as_float(regs[j + 1]) * zv.y;
                    C[(size_t)(n0 + cc + j + 2) * M_TOTAL + m] = __uint_as_float(regs[j + 2]) * zv.z;
                    C[(size_t)(n0 + cc + j + 3) * M_TOTAL + m] = __uint_as_float(regs[j + 3]) * zv.w;
                }
            }
        }
    }

    __syncthreads();
    if (wid == 0) TCGEN05_DEALLOC(tmem, 256);
}

// ---------------------------------------------------------------------------
// elementwise bf16 hi/lo split: fp32 -> (hi, lo)
// ---------------------------------------------------------------------------
__global__ void __launch_bounds__(256)
split_bf16(const float* __restrict__ in, __nv_bfloat16* __restrict__ ohi,
           __nv_bfloat16* __restrict__ olo, size_t n4)
{
    size_t i = (size_t)blockIdx.x * blockDim.x + threadIdx.x;
    size_t stride = (size_t)gridDim.x * blockDim.x;
    for (; i < n4; i += stride) {
        float4 v = ((const float4*)in)[i];
        float hx = bf16hi(v.x), hy = bf16hi(v.y), hz = bf16hi(v.z), hw = bf16hi(v.w);
        ((uint2*)ohi)[i] = make_uint2(bf16pack(v.x, v.y), bf16pack(v.z, v.w));
        ((uint2*)olo)[i] = make_uint2(bf16pack(v.x - hx, v.y - hy),
                                      bf16pack(v.z - hz, v.w - hw));
    }
}

// ---------------------------------------------------------------------------
// 32x32 tiled transpose + bf16 split: in[R][C] fp32 -> hi/lo bf16 [C][R]
// ---------------------------------------------------------------------------
__global__ void __launch_bounds__(256)
transpose_split_bf16(const float* __restrict__ in, __nv_bfloat16* __restrict__ oh,
                     __nv_bfloat16* __restrict__ ol, int R, int C)
{
    __shared__ float t[32][33];
    int c0 = blockIdx.x * 32, r0 = blockIdx.y * 32;
    int tx = threadIdx.x, ty = threadIdx.y;
#pragma unroll
    for (int i = 0; i < 32; i += 8)
        t[ty + i][tx] = in[(size_t)(r0 + ty + i) * C + c0 + tx];
    __syncthreads();
#pragma unroll
    for (int i = 0; i < 32; i += 8) {
        float v = t[tx][ty + i];
        float h = bf16hi(v);
        size_t off = (size_t)(c0 + ty + i) * R + r0 + tx;
        oh[off] = __float2bfloat16_rn(v);
        ol[off] = __float2bfloat16_rn(v - h);
    }
}

// ---------------------------------------------------------------------------
// Gated linear scan: block per (channel, batch, dir)
// ---------------------------------------------------------------------------
__global__ __launch_bounds__(256)
void scan_kernel()
{
    int d = blockIdx.x, bb = blockIdx.y, dir = blockIdx.z;
    const float* dptr = &g_dg[(size_t)(dir * 512 + d)       * M_TOTAL + bb * L_SEQ];
    const float* gptr = &g_dg[(size_t)(dir * 512 + 256 + d) * M_TOTAL + bb * L_SEQ];
    float*       hptr = &g_h [(size_t)(dir * 256 + d)       * M_TOTAL + bb * L_SEQ];

    int tid = threadIdx.x;
    int base = (dir == 0) ? tid * 16 : (L_SEQ - 16 * (tid + 1));

    float tmpd[16], tmpg[16];
#pragma unroll
    for (int q = 0; q < 4; q++) {
        *(float4*)&tmpd[q * 4] = *(const float4*)&dptr[base + q * 4];
        *(float4*)&tmpg[q * 4] = *(const float4*)&gptr[base + q * 4];
    }
    float dl[16], gt[16];
#pragma unroll
    for (int e = 0; e < 16; e++) {
        int src = (dir == 0) ? e : (15 - e);
        dl[e] = tmpd[src];
        gt[e] = tmpg[src];
    }

    float Aseg = 1.f, Bseg = 0.f;
#pragma unroll
    for (int e = 0; e < 16; e++) {
        Aseg = Aseg * dl[e];
        Bseg = fmaf(Bseg, dl[e], gt[e]);
    }

    __shared__ float sA[256], sB[256];
    sA[tid] = Aseg; sB[tid] = Bseg;
    __syncthreads();
#pragma unroll
    for (int off = 1; off < 256; off <<= 1) {
        float pA = 0.f, pB = 0.f;
        bool has = (tid >= off);
        if (has) { pA = sA[tid - off]; pB = sB[tid - off]; }
        __syncthreads();
        if (has) {
            float Ac = sA[tid], Bc = sB[tid];
            sA[tid] = Ac * pA;
            sB[tid] = fmaf(Ac, pB, Bc);
        }
        __syncthreads();
    }

    float h = (tid == 0) ? 0.f : sB[tid - 1];
    float hv[16];
#pragma unroll
    for (int e = 0; e < 16; e++) {
        h = fmaf(h, dl[e], gt[e]);
        hv[e] = h;
    }

    float outv[16];
#pragma unroll
    for (int q = 0; q < 16; q++)
        outv[q] = (dir == 0) ? hv[q] : hv[15 - q];
#pragma unroll
    for (int q = 0; q < 4; q++)
        *(float4*)&hptr[base + q * 4] =
            make_float4(outv[q * 4], outv[q * 4 + 1], outv[q * 4 + 2], outv[q * 4 + 3]);
}

// ---------------------------------------------------------------------------
// LayerNorm over D=2048 per row
// ---------------------------------------------------------------------------
__global__ __launch_bounds__(256)
void ln_kernel(const float* __restrict__ gamma, const float* __restrict__ beta,
               float* __restrict__ out)
{
    int row = blockIdx.x;
    int tid = threadIdx.x;
    const float* yrow = &g_out[(size_t)row * D_DIM];

    float v[8];
    *(float4*)&v[0] = *(const float4*)&yrow[tid * 8];
    *(float4*)&v[4] = *(const float4*)&yrow[tid * 8 + 4];

    float s = 0.f, s2 = 0.f;
#pragma unroll
    for (int e = 0; e < 8; e++) { s += v[e]; s2 = fmaf(v[e], v[e], s2); }

#pragma unroll
    for (int o = 16; o > 0; o >>= 1) {
        s  += __shfl_xor_sync(0xffffffffu, s,  o);
        s2 += __shfl_xor_sync(0xffffffffu, s2, o);
    }
    __shared__ float sh[16];
    int w = tid >> 5, lane = tid & 31;
    if (lane == 0) { sh[w] = s; sh[8 + w] = s2; }
    __syncthreads();
    float S = 0.f, S2 = 0.f;
    if (lane < 8) { S = sh[lane]; S2 = sh[8 + lane]; }
#pragma unroll
    for (int o = 4; o > 0; o >>= 1) {
        S  += __shfl_xor_sync(0xffffffffu, S,  o);
        S2 += __shfl_xor_sync(0xffffffffu, S2, o);
    }
    S  = __shfl_sync(0xffffffffu, S,  0);
    S2 = __shfl_sync(0xffffffffu, S2, 0);

    const float invD = 1.f / (float)D_DIM;
    float mu = S * invD;
    float var = fmaf(S2, invD, -mu * mu);
    float inv = rsqrtf(var + LN_EPS);

    float g[8], be[8];
    *(float4*)&g[0]  = *(const float4*)&gamma[tid * 8];
    *(float4*)&g[4]  = *(const float4*)&gamma[tid * 8 + 4];
    *(float4*)&be[0] = *(const float4*)&beta[tid * 8];
    *(float4*)&be[4] = *(const float4*)&beta[tid * 8 + 4];

    float r[8];
#pragma unroll
    for (int e = 0; e < 8; e++)
        r[e] = fmaf((v[e] - mu) * inv, g[e], be[e]);

    float* orow = &out[(size_t)row * D_DIM];
    *(float4*)&orow[tid * 8]     = make_float4(r[0], r[1], r[2], r[3]);
    *(float4*)&orow[tid * 8 + 4] = make_float4(r[4], r[5], r[6], r[7]);
}

// ---------------------------------------------------------------------------
extern "C" void kernel_launch(void* const* d_in, const int* in_sizes, int n_in,
                              void* d_out, int out_size)
{
    const float* x     = (const float*)d_in[0];
    const float* W_in  = (const float*)d_in[1];
    const float* W_fwd = (const float*)d_in[2];
    const float* W_bwd = (const float*)d_in[3];
    const float* W_out = (const float*)d_in[4];
    const float* gamma = (const float*)d_in[5];
    const float* beta  = (const float*)d_in[6];
    float* out = (float*)d_out;

    float *zp, *dgp, *hp, *op;
    __nv_bfloat16 *xh, *xl, *zh, *zl, *hh, *hl, *w1h, *w1l, *w2h, *w2l, *w3h, *w3l;
    cudaGetSymbolAddress((void**)&zp,  g_z);
    cudaGetSymbolAddress((void**)&dgp, g_dg);
    cudaGetSymbolAddress((void**)&hp,  g_h);
    cudaGetSymbolAddress((void**)&op,  g_out);
    cudaGetSymbolAddress((void**)&xh,  g_xh);
    cudaGetSymbolAddress((void**)&xl,  g_xl);
    cudaGetSymbolAddress((void**)&zh,  g_zh);
    cudaGetSymbolAddress((void**)&zl,  g_zl);
    cudaGetSymbolAddress((void**)&hh,  g_hh);
    cudaGetSymbolAddress((void**)&hl,  g_hl);
    cudaGetSymbolAddress((void**)&w1h, g_w1h);
    cudaGetSymbolAddress((void**)&w1l, g_w1l);
    cudaGetSymbolAddress((void**)&w2h, g_w2h);
    cudaGetSymbolAddress((void**)&w2l, g_w2l);
    cudaGetSymbolAddress((void**)&w3h, g_w3h);
    cudaGetSymbolAddress((void**)&w3l, g_w3l);

    cudaFuncSetAttribute(gemm_bf16x3<0>, cudaFuncAttributeMaxDynamicSharedMemorySize, GSMEM);
    cudaFuncSetAttribute(gemm_bf16x3<2>, cudaFuncAttributeMaxDynamicSharedMemorySize, GSMEM);
    cudaFuncSetAttribute(gemm_bf16x3<3>, cudaFuncAttributeMaxDynamicSharedMemorySize, GSMEM);

    dim3 tb(32, 8);

    // operand preparation: x split; weights transpose+split to K-major bf16
    split_bf16<<<2048, 256>>>(x, xh, xl, (size_t)M_TOTAL * D_DIM / 4);
    transpose_split_bf16<<<dim3(DI_DIM / 32, D_DIM / 32), tb>>>(W_in, w1h, w1l, D_DIM, DI_DIM);
    transpose_split_bf16<<<dim3(512 / 32, DI_DIM / 32), tb>>>(W_fwd, w2h, w2l, DI_DIM, 512);
    transpose_split_bf16<<<dim3(512 / 32, DI_DIM / 32), tb>>>(
        W_bwd, w2h + (size_t)512 * DI_DIM, w2l + (size_t)512 * DI_DIM, DI_DIM, 512);
    transpose_split_bf16<<<dim3(D_DIM / 32, 512 / 32), tb>>>(W_out, w3h, w3l, 512, D_DIM);

    // z = x @ W_in  (fp32 + bf16 hi/lo epilogue)
    gemm_bf16x3<0><<<dim3(1, M_TOTAL / 128), 256, GSMEM>>>(
        xh, xl, w1h, w1l, zp, zh, zl, nullptr, DI_DIM, D_DIM);

    // dg^T = act(z @ [W_fwd|W_bwd])^T
    gemm_bf16x3<2><<<dim3(4, M_TOTAL / 128), 256, GSMEM>>>(
        zh, zl, w2h, w2l, dgp, nullptr, nullptr, zp, 1024, DI_DIM);

    // bidirectional gated scans -> h^T
    scan_kernel<<<dim3(DI_DIM, 4, 2), 256>>>();

    // h^T -> h row-major bf16 hi/lo
    transpose_split_bf16<<<dim3(M_TOTAL / 32, 512 / 32), tb>>>(hp, hh, hl, 512, M_TOTAL);

    // y = h @ W_out + x
    gemm_bf16x3<3><<<dim3(8, M_TOTAL / 128), 256, GSMEM>>>(
        hh, hl, w3h, w3l, op, nullptr, nullptr, x, D_DIM, 512);

    // LayerNorm
    ln_kernel<<<M_TOTAL, 256>>>(gamma, beta, out);
}

// round 6
// speedup vs baseline: 4.0018x; 1.0182x over previous
#include <cuda_runtime.h>
#include <cuda_bf16.h>
#include <math.h>
#include <stdint.h>

#define M_TOTAL 16384
#define D_DIM   2048
#define DI_DIM  256
#define L_SEQ   4096
#define LN_EPS  1e-5f

// ---------------- scratch ----------------
__device__ float g_z  [(size_t)M_TOTAL * DI_DIM];     // z fp32 row-major (gating)
__device__ float g_dg [(size_t)1024 * M_TOTAL];       // dg^T
__device__ float g_h  [(size_t)512  * M_TOTAL];       // h^T fp32
__device__ float g_out[(size_t)M_TOTAL * D_DIM];      // y = out + x

__device__ __nv_bfloat16 g_xh [(size_t)M_TOTAL * D_DIM];
__device__ __nv_bfloat16 g_xl [(size_t)M_TOTAL * D_DIM];
__device__ __nv_bfloat16 g_zh [(size_t)M_TOTAL * DI_DIM];
__device__ __nv_bfloat16 g_zl [(size_t)M_TOTAL * DI_DIM];
__device__ __nv_bfloat16 g_hh [(size_t)M_TOTAL * 512];
__device__ __nv_bfloat16 g_hl [(size_t)M_TOTAL * 512];
__device__ __nv_bfloat16 g_w1h[(size_t)DI_DIM * D_DIM];
__device__ __nv_bfloat16 g_w1l[(size_t)DI_DIM * D_DIM];
__device__ __nv_bfloat16 g_w2h[(size_t)1024 * DI_DIM];
__device__ __nv_bfloat16 g_w2l[(size_t)1024 * DI_DIM];
__device__ __nv_bfloat16 g_w3h[(size_t)D_DIM * 512];
__device__ __nv_bfloat16 g_w3l[(size_t)D_DIM * 512];

// ---------------- arch feature gate ----------------
#if defined(__CUDA_ARCH_FEAT_SM103_ALL) || defined(__CUDA_ARCH_FEAT_SM100_ALL) || \
    defined(__CUDA_ARCH_FEAT_SM101_ALL) || defined(__CUDA_ARCH_SPECIFIC__)
#define TC_OK 1
#else
#define TC_OK 0
#endif

// ---------------- helpers ----------------
__device__ __forceinline__ uint32_t smem_u32(const void* p) {
    uint32_t a;
    asm("{ .reg .u64 t; cvta.to.shared.u64 t, %1; cvt.u32.u64 %0, t; }" : "=r"(a) : "l"(p));
    return a;
}

__device__ __forceinline__ float bf16hi(float a) {
    return __bfloat162float(__float2bfloat16_rn(a));
}
__device__ __forceinline__ uint32_t bf16pack(float a, float b) {
    __nv_bfloat162 t = __floats2bfloat162_rn(a, b);
    return *reinterpret_cast<uint32_t*>(&t);
}

#define CP_ASYNC16(dst, src) \
    asm volatile("cp.async.cg.shared.global [%0], [%1], 16;" :: "r"(dst), "l"(src))
#define CP_COMMIT() asm volatile("cp.async.commit_group;" ::: "memory")
#define CP_WAIT1()  asm volatile("cp.async.wait_group 1;" ::: "memory")
#define CP_WAIT2()  asm volatile("cp.async.wait_group 2;" ::: "memory")

#define MBARRIER_INIT(addr, cnt) \
    asm volatile("mbarrier.init.shared.b64 [%0], %1;" :: "r"(addr), "r"(cnt) : "memory")

__device__ __forceinline__ void mbar_wait(uint32_t mbar, uint32_t parity) {
    asm volatile(
        "{\n\t.reg .pred P;\n\t"
        "W0_%=:\n\t"
        "mbarrier.try_wait.parity.acquire.cta.shared::cta.b64 P, [%0], %1, 0x989680;\n\t"
        "@P bra W1_%=;\n\t"
        "bra W0_%=;\n\t"
        "W1_%=:\n\t}"
        :: "r"(mbar), "r"(parity) : "memory");
}

#define FENCE_ASYNC_SHARED() \
    asm volatile("fence.proxy.async.shared::cta;" ::: "memory")

#if TC_OK
#define TCGEN05_ALLOC(smem_res, ncols) \
    asm volatile("tcgen05.alloc.cta_group::1.sync.aligned.shared::cta.b32 [%0], %1;" \
                 :: "r"((uint32_t)(smem_res)), "r"((uint32_t)(ncols)) : "memory")
#define TCGEN05_DEALLOC(tmem, ncols) \
    asm volatile("tcgen05.dealloc.cta_group::1.sync.aligned.b32 %0, %1;" \
                 :: "r"(tmem), "r"((uint32_t)(ncols)))
#define TCGEN05_RELINQUISH() \
    asm volatile("tcgen05.relinquish_alloc_permit.cta_group::1.sync.aligned;")
#define TCGEN05_COMMIT(mbar) \
    asm volatile("tcgen05.commit.cta_group::1.mbarrier::arrive::one.shared::cluster.b64 [%0];" \
                 :: "r"((uint32_t)(mbar)) : "memory")
#define TCGEN05_FENCE_AFTER() \
    asm volatile("tcgen05.fence::after_thread_sync;" ::: "memory")
#define TCGEN05_WAIT_LD() \
    asm volatile("tcgen05.wait::ld.sync.aligned;" ::: "memory")

#define TCGEN05_LD_X32(r, tmem_addr) \
    asm volatile( \
        "tcgen05.ld.sync.aligned.32x32b.x32.b32 " \
        "{%0, %1, %2, %3, %4, %5, %6, %7, " \
        " %8, %9, %10, %11, %12, %13, %14, %15, " \
        " %16, %17, %18, %19, %20, %21, %22, %23, " \
        " %24, %25, %26, %27, %28, %29, %30, %31}, [%32];" \
        : "=r"((r)[0]),  "=r"((r)[1]),  "=r"((r)[2]),  "=r"((r)[3]), \
          "=r"((r)[4]),  "=r"((r)[5]),  "=r"((r)[6]),  "=r"((r)[7]), \
          "=r"((r)[8]),  "=r"((r)[9]),  "=r"((r)[10]), "=r"((r)[11]), \
          "=r"((r)[12]), "=r"((r)[13]), "=r"((r)[14]), "=r"((r)[15]), \
          "=r"((r)[16]), "=r"((r)[17]), "=r"((r)[18]), "=r"((r)[19]), \
          "=r"((r)[20]), "=r"((r)[21]), "=r"((r)[22]), "=r"((r)[23]), \
          "=r"((r)[24]), "=r"((r)[25]), "=r"((r)[26]), "=r"((r)[27]), \
          "=r"((r)[28]), "=r"((r)[29]), "=r"((r)[30]), "=r"((r)[31]) \
        : "r"(tmem_addr))

__device__ __forceinline__ void mma_bf16(uint32_t d, uint64_t ad, uint64_t bd,
                                         uint32_t idesc, uint32_t en) {
    asm volatile(
        "{\n\t.reg .pred p;\n\t"
        "setp.ne.u32 p, %5, 0;\n\t"
        "tcgen05.mma.cta_group::1.kind::f16 [%0], %1, %2, %3, {%4, %4, %4, %4}, p;\n\t}"
        :: "r"(d), "l"(ad), "l"(bd), "r"(idesc), "r"(0u), "r"(en) : "memory");
}
#else
#define TCGEN05_ALLOC(smem_res, ncols)  do {} while (0)
#define TCGEN05_DEALLOC(tmem, ncols)    do {} while (0)
#define TCGEN05_RELINQUISH()            do {} while (0)
#define TCGEN05_COMMIT(mbar)            do {} while (0)
#define TCGEN05_FENCE_AFTER()           do {} while (0)
#define TCGEN05_WAIT_LD()               do {} while (0)
#define TCGEN05_LD_X32(r, tmem_addr) \
    do { _Pragma("unroll") for (int _i = 0; _i < 32; _i++) (r)[_i] = 0u; } while (0)
__device__ __forceinline__ void mma_bf16(uint32_t, uint64_t, uint64_t, uint32_t, uint32_t) {}
#endif

// SW128 K-major SMEM descriptor (layout=2, ver=1, SBO=64, LBO=1)
__device__ __forceinline__ uint64_t sdesc(uint32_t addr) {
    return 0x4000404000010000ULL | (uint64_t)((addr >> 4) & 0x3FFF);
}

#define STG_OFF 1024
// idesc kind::f16 bf16: dtype=F32(1@4), atype=BF16(1@7), btype=BF16(1@10), N/8@17, M/16@24
#define IDESC_BF16 ((1u << 4) | (1u << 7) | (1u << 10) | ((256u / 8) << 17) | ((128u / 16) << 24))

// ---------------------------------------------------------------------------
// bf16x3 Ootomo GEMM, BK=32 fp elems per chunk, hi|lo packed in 128B SW128 rows
// (hi bytes [0,64) -> desc +0/+2, lo bytes [64,128) -> desc +4/+6).
// Tile (MB*128) x 256, MB TMEM accumulators of 256 cols, DEPTH-stage cp.async
// pipeline (load(c+DEPTH-1) gated on MMA(c-1) -> one chunk of slack).
// MODE 0: row-major fp32 + bf16 hi/lo split store (z producer)
// MODE 2: delta/gate epilogue, transposed store into dg^T (EX = z fp32)
// MODE 3: row-major store + residual EX
// ---------------------------------------------------------------------------
template<int MODE, int MB, int DEPTH>
__global__ void __launch_bounds__(256)
gemm_bf16x3(const __nv_bfloat16* __restrict__ Ah, const __nv_bfloat16* __restrict__ Al,
            const __nv_bfloat16* __restrict__ Bh, const __nv_bfloat16* __restrict__ Bl,
            float* __restrict__ C, __nv_bfloat16* __restrict__ Chi,
            __nv_bfloat16* __restrict__ Clo, const float* __restrict__ EX,
            int N, int K)
{
    constexpr int ABYTES = MB * 16384;      // A stage bytes (hi|lo packed rows)
    constexpr int STAGE  = ABYTES + 32768;  // + B (256 rows x 128B)
    constexpr int NCOLS  = MB * 256;

    extern __shared__ __align__(1024) char dsm[];
    uint32_t sb = smem_u32(dsm);
    int tid = threadIdx.x, wid = tid >> 5, lane = tid & 31;
    int n0 = blockIdx.x * 256, m0 = blockIdx.y * (MB * 128);

    if (wid == 0) TCGEN05_ALLOC(sb, NCOLS);
    if (tid == 0) {
#pragma unroll
        for (int s = 0; s < DEPTH; s++) MBARRIER_INIT(sb + 16 + 8 * s, 1);
    }
    __syncthreads();
    uint32_t tmem;
    asm volatile("ld.shared.b32 %0, [%1];" : "=r"(tmem) : "r"(sb));
    if (wid == 0) TCGEN05_RELINQUISH();

    const int NC = K >> 5;                  // 32-element K chunks (NC >= DEPTH+1 everywhere)
    const int k8 = tid & 7;                 // 16B segment within 128B row
    const int rb = tid >> 3;                // row 0..31
    const int kseg = (k8 & 3) * 8;          // element offset within the 32-elem chunk
    const __nv_bfloat16* Asrc = (k8 < 4) ? Ah : Al;   // hi -> bytes [0,64), lo -> [64,128)
    const __nv_bfloat16* Bsrc = (k8 < 4) ? Bh : Bl;

    auto load_tiles = [&](int c, int stage) {
        int kc = c * 32;
        uint32_t sa = sb + STG_OFF + stage * STAGE;
#pragma unroll
        for (int i = 0; i < MB * 4; i++) {               // A: MB*128 rows
            int r = rb + 32 * i;
            uint32_t byte = r * 128 + k8 * 16;
            uint32_t sw = byte ^ ((byte >> 3) & 0x70);
            CP_ASYNC16(sa + sw, (const void*)(Asrc + (size_t)(m0 + r) * K + kc + kseg));
        }
#pragma unroll
        for (int i = 0; i < 8; i++) {                    // B: 256 rows
            int r = rb + 32 * i;
            uint32_t byte = r * 128 + k8 * 16;
            uint32_t sw = byte ^ ((byte >> 3) & 0x70);
            CP_ASYNC16(sa + ABYTES + sw, (const void*)(Bsrc + (size_t)(n0 + r) * K + kc + kseg));
        }
        CP_COMMIT();
    };

#pragma unroll
    for (int s = 0; s < DEPTH - 1; s++) load_tiles(s, s);

    for (int c = 0; c < NC; c++) {
        int st = c % DEPTH;
        if constexpr (DEPTH == 4) { CP_WAIT2(); } else { CP_WAIT1(); }
        FENCE_ASYNC_SHARED();
        __syncthreads();
        if (tid == 0) {
            uint32_t sa = sb + STG_OFF + st * STAGE;
            uint64_t bd = sdesc(sa + ABYTES);
#pragma unroll
            for (int mb = 0; mb < MB; mb++) {
                uint64_t ad = sdesc(sa + mb * 16384);
                uint32_t dt = tmem + mb * 256;
#pragma unroll
                for (int k = 0; k < 2; k++)              // hi*hi
                    mma_bf16(dt, ad + 2 * k, bd + 2 * k, IDESC_BF16, (uint32_t)((c | k) != 0));
#pragma unroll
                for (int k = 0; k < 2; k++)              // hi*lo
                    mma_bf16(dt, ad + 2 * k, bd + 4 + 2 * k, IDESC_BF16, 1u);
#pragma unroll
                for (int k = 0; k < 2; k++)              // lo*hi
                    mma_bf16(dt, ad + 4 + 2 * k, bd + 2 * k, IDESC_BF16, 1u);
            }
            TCGEN05_COMMIT(sb + 16 + 8 * st);
        }
        if (c + DEPTH - 1 < NC) {
            if (c >= 1)   // stage (c+DEPTH-1)%DEPTH last used by MMA(c-1)
                mbar_wait(sb + 16 + 8 * ((c - 1) % DEPTH), (uint32_t)(((c - 1) / DEPTH) & 1));
            load_tiles(c + DEPTH - 1, (c + DEPTH - 1) % DEPTH);
        } else {
            CP_COMMIT();  // empty group keeps wait accounting exact
        }
    }
    mbar_wait(sb + 16 + 8 * ((NC - 1) % DEPTH), (uint32_t)(((NC - 1) / DEPTH) & 1));
    TCGEN05_FENCE_AFTER();

    // -------- epilogue --------
    int mrow, ccb, ccend;
    uint32_t tb;
    if constexpr (MB == 2) {        // warp w -> rows (w&3)*32 + (w>>2)*128, all 256 cols
        mrow = (wid & 3) * 32 + lane + (wid >> 2) * 128;
        ccb = 0; ccend = 256;
        tb = tmem + (wid >> 2) * 256;
    } else {                        // warp w -> rows (w&3)*32, col half (w>>2)*128
        mrow = (wid & 3) * 32 + lane;
        ccb = (wid >> 2) * 128; ccend = ccb + 128;
        tb = tmem;
    }
    int m = m0 + mrow;
    uint32_t regs[32];
#pragma unroll
    for (int cc = ccb; cc < ccend; cc += 32) {
        TCGEN05_LD_X32(regs, tb + cc);
        TCGEN05_WAIT_LD();

        if (MODE == 0) {
#pragma unroll
            for (int j = 0; j < 32; j += 4) {
                size_t off = (size_t)m * N + n0 + cc + j;
                float4 v = make_float4(__uint_as_float(regs[j]),
                                       __uint_as_float(regs[j + 1]),
                                       __uint_as_float(regs[j + 2]),
                                       __uint_as_float(regs[j + 3]));
                *(float4*)&C[off] = v;
                float hx = bf16hi(v.x), hy = bf16hi(v.y), hz = bf16hi(v.z), hw = bf16hi(v.w);
                *(uint2*)&Chi[off] = make_uint2(bf16pack(v.x, v.y), bf16pack(v.z, v.w));
                *(uint2*)&Clo[off] = make_uint2(bf16pack(v.x - hx, v.y - hy),
                                                bf16pack(v.z - hz, v.w - hw));
            }
        } else if (MODE == 3) {
#pragma unroll
            for (int j = 0; j < 32; j += 4) {
                size_t off = (size_t)m * N + n0 + cc + j;
                float4 v = make_float4(__uint_as_float(regs[j]),
                                       __uint_as_float(regs[j + 1]),
                                       __uint_as_float(regs[j + 2]),
                                       __uint_as_float(regs[j + 3]));
                float4 r4 = *(const float4*)&EX[off];
                v.x += r4.x; v.y += r4.y; v.z += r4.z; v.w += r4.w;
                *(float4*)&C[off] = v;
            }
        } else {  // MODE 2: delta/gate, transposed store into dg^T
            int jj0 = (n0 + cc) & 511;
            if (jj0 < 256) {
#pragma unroll
                for (int j = 0; j < 32; j++) {
                    float v = __uint_as_float(regs[j]);
                    v = 1.f / (1.f + expf(-v));
                    C[(size_t)(n0 + cc + j) * M_TOTAL + m] = v;
                }
            } else {
                int ch0 = jj0 - 256;
#pragma unroll
                for (int j = 0; j < 32; j += 4) {
                    float4 zv = *(const float4*)&EX[(size_t)m * DI_DIM + ch0 + j];
                    C[(size_t)(n0 + cc + j + 0) * M_TOTAL + m] = __uint_as_float(regs[j + 0]) * zv.x;
                    C[(size_t)(n0 + cc + j + 1) * M_TOTAL + m] = __uint_as_float(regs[j + 1]) * zv.y;
                    C[(size_t)(n0 + cc + j + 2) * M_TOTAL + m] = __uint_as_float(regs[j + 2]) * zv.z;
                    C[(size_t)(n0 + cc + j + 3) * M_TOTAL + m] = __uint_as_float(regs[j + 3]) * zv.w;
                }
            }
        }
    }

    __syncthreads();
    if (wid == 0) TCGEN05_DEALLOC(tmem, NCOLS);
}

// ---------------------------------------------------------------------------
// elementwise bf16 hi/lo split: fp32 -> (hi, lo)
// ---------------------------------------------------------------------------
__global__ void __launch_bounds__(256)
split_bf16(const float* __restrict__ in, __nv_bfloat16* __restrict__ ohi,
           __nv_bfloat16* __restrict__ olo, size_t n4)
{
    size_t i = (size_t)blockIdx.x * blockDim.x + threadIdx.x;
    size_t stride = (size_t)gridDim.x * blockDim.x;
    for (; i < n4; i += stride) {
        float4 v = ((const float4*)in)[i];
        float hx = bf16hi(v.x), hy = bf16hi(v.y), hz = bf16hi(v.z), hw = bf16hi(v.w);
        ((uint2*)ohi)[i] = make_uint2(bf16pack(v.x, v.y), bf16pack(v.z, v.w));
        ((uint2*)olo)[i] = make_uint2(bf16pack(v.x - hx, v.y - hy),
                                      bf16pack(v.z - hz, v.w - hw));
    }
}

// ---------------------------------------------------------------------------
// 32x32 tiled transpose + bf16 split: in[R][C] fp32 -> hi/lo bf16 [C][R]
// ---------------------------------------------------------------------------
__global__ void __launch_bounds__(256)
transpose_split_bf16(const float* __restrict__ in, __nv_bfloat16* __restrict__ oh,
                     __nv_bfloat16* __restrict__ ol, int R, int C)
{
    __shared__ float t[32][33];
    int c0 = blockIdx.x * 32, r0 = blockIdx.y * 32;
    int tx = threadIdx.x, ty = threadIdx.y;
#pragma unroll
    for (int i = 0; i < 32; i += 8)
        t[ty + i][tx] = in[(size_t)(r0 + ty + i) * C + c0 + tx];
    __syncthreads();
#pragma unroll
    for (int i = 0; i < 32; i += 8) {
        float v = t[tx][ty + i];
        float h = bf16hi(v);
        size_t off = (size_t)(c0 + ty + i) * R + r0 + tx;
        oh[off] = __float2bfloat16_rn(v);
        ol[off] = __float2bfloat16_rn(v - h);
    }
}

// ---------------------------------------------------------------------------
// Gated linear scan: block per (channel, batch, dir)
// ---------------------------------------------------------------------------
__global__ __launch_bounds__(256)
void scan_kernel()
{
    int d = blockIdx.x, bb = blockIdx.y, dir = blockIdx.z;
    const float* dptr = &g_dg[(size_t)(dir * 512 + d)       * M_TOTAL + bb * L_SEQ];
    const float* gptr = &g_dg[(size_t)(dir * 512 + 256 + d) * M_TOTAL + bb * L_SEQ];
    float*       hptr = &g_h [(size_t)(dir * 256 + d)       * M_TOTAL + bb * L_SEQ];

    int tid = threadIdx.x;
    int base = (dir == 0) ? tid * 16 : (L_SEQ - 16 * (tid + 1));

    float tmpd[16], tmpg[16];
#pragma unroll
    for (int q = 0; q < 4; q++) {
        *(float4*)&tmpd[q * 4] = *(const float4*)&dptr[base + q * 4];
        *(float4*)&tmpg[q * 4] = *(const float4*)&gptr[base + q * 4];
    }
    float dl[16], gt[16];
#pragma unroll
    for (int e = 0; e < 16; e++) {
        int src = (dir == 0) ? e : (15 - e);
        dl[e] = tmpd[src];
        gt[e] = tmpg[src];
    }

    float Aseg = 1.f, Bseg = 0.f;
#pragma unroll
    for (int e = 0; e < 16; e++) {
        Aseg = Aseg * dl[e];
        Bseg = fmaf(Bseg, dl[e], gt[e]);
    }

    __shared__ float sA[256], sB[256];
    sA[tid] = Aseg; sB[tid] = Bseg;
    __syncthreads();
#pragma unroll
    for (int off = 1; off < 256; off <<= 1) {
        float pA = 0.f, pB = 0.f;
        bool has = (tid >= off);
        if (has) { pA = sA[tid - off]; pB = sB[tid - off]; }
        __syncthreads();
        if (has) {
            float Ac = sA[tid], Bc = sB[tid];
            sA[tid] = Ac * pA;
            sB[tid] = fmaf(Ac, pB, Bc);
        }
        __syncthreads();
    }

    float h = (tid == 0) ? 0.f : sB[tid - 1];
    float hv[16];
#pragma unroll
    for (int e = 0; e < 16; e++) {
        h = fmaf(h, dl[e], gt[e]);
        hv[e] = h;
    }

    float outv[16];
#pragma unroll
    for (int q = 0; q < 16; q++)
        outv[q] = (dir == 0) ? hv[q] : hv[15 - q];
#pragma unroll
    for (int q = 0; q < 4; q++)
        *(float4*)&hptr[base + q * 4] =
            make_float4(outv[q * 4], outv[q * 4 + 1], outv[q * 4 + 2], outv[q * 4 + 3]);
}

// ---------------------------------------------------------------------------
// LayerNorm over D=2048 per row
// ---------------------------------------------------------------------------
__global__ __launch_bounds__(256)
void ln_kernel(const float* __restrict__ gamma, const float* __restrict__ beta,
               float* __restrict__ out)
{
    int row = blockIdx.x;
    int tid = threadIdx.x;
    const float* yrow = &g_out[(size_t)row * D_DIM];

    float v[8];
    *(float4*)&v[0] = *(const float4*)&yrow[tid * 8];
    *(float4*)&v[4] = *(const float4*)&yrow[tid * 8 + 4];

    float s = 0.f, s2 = 0.f;
#pragma unroll
    for (int e = 0; e < 8; e++) { s += v[e]; s2 = fmaf(v[e], v[e], s2); }

#pragma unroll
    for (int o = 16; o > 0; o >>= 1) {
        s  += __shfl_xor_sync(0xffffffffu, s,  o);
        s2 += __shfl_xor_sync(0xffffffffu, s2, o);
    }
    __shared__ float sh[16];
    int w = tid >> 5, lane = tid & 31;
    if (lane == 0) { sh[w] = s; sh[8 + w] = s2; }
    __syncthreads();
    float S = 0.f, S2 = 0.f;
    if (lane < 8) { S = sh[lane]; S2 = sh[8 + lane]; }
#pragma unroll
    for (int o = 4; o > 0; o >>= 1) {
        S  += __shfl_xor_sync(0xffffffffu, S,  o);
        S2 += __shfl_xor_sync(0xffffffffu, S2, o);
    }
    S  = __shfl_sync(0xffffffffu, S,  0);
    S2 = __shfl_sync(0xffffffffu, S2, 0);

    const float invD = 1.f / (float)D_DIM;
    float mu = S * invD;
    float var = fmaf(S2, invD, -mu * mu);
    float inv = rsqrtf(var + LN_EPS);

    float g[8], be[8];
    *(float4*)&g[0]  = *(const float4*)&gamma[tid * 8];
    *(float4*)&g[4]  = *(const float4*)&gamma[tid * 8 + 4];
    *(float4*)&be[0] = *(const float4*)&beta[tid * 8];
    *(float4*)&be[4] = *(const float4*)&beta[tid * 8 + 4];

    float r[8];
#pragma unroll
    for (int e = 0; e < 8; e++)
        r[e] = fmaf((v[e] - mu) * inv, g[e], be[e]);

    float* orow = &out[(size_t)row * D_DIM];
    *(float4*)&orow[tid * 8]     = make_float4(r[0], r[1], r[2], r[3]);
    *(float4*)&orow[tid * 8 + 4] = make_float4(r[4], r[5], r[6], r[7]);
}

// ---------------------------------------------------------------------------
extern "C" void kernel_launch(void* const* d_in, const int* in_sizes, int n_in,
                              void* d_out, int out_size)
{
    const float* x     = (const float*)d_in[0];
    const float* W_in  = (const float*)d_in[1];
    const float* W_fwd = (const float*)d_in[2];
    const float* W_bwd = (const float*)d_in[3];
    const float* W_out = (const float*)d_in[4];
    const float* gamma = (const float*)d_in[5];
    const float* beta  = (const float*)d_in[6];
    float* out = (float*)d_out;

    float *zp, *dgp, *hp, *op;
    __nv_bfloat16 *xh, *xl, *zh, *zl, *hh, *hl, *w1h, *w1l, *w2h, *w2l, *w3h, *w3l;
    cudaGetSymbolAddress((void**)&zp,  g_z);
    cudaGetSymbolAddress((void**)&dgp, g_dg);
    cudaGetSymbolAddress((void**)&hp,  g_h);
    cudaGetSymbolAddress((void**)&op,  g_out);
    cudaGetSymbolAddress((void**)&xh,  g_xh);
    cudaGetSymbolAddress((void**)&xl,  g_xl);
    cudaGetSymbolAddress((void**)&zh,  g_zh);
    cudaGetSymbolAddress((void**)&zl,  g_zl);
    cudaGetSymbolAddress((void**)&hh,  g_hh);
    cudaGetSymbolAddress((void**)&hl,  g_hl);
    cudaGetSymbolAddress((void**)&w1h, g_w1h);
    cudaGetSymbolAddress((void**)&w1l, g_w1l);
    cudaGetSymbolAddress((void**)&w2h, g_w2h);
    cudaGetSymbolAddress((void**)&w2l, g_w2l);
    cudaGetSymbolAddress((void**)&w3h, g_w3h);
    cudaGetSymbolAddress((void**)&w3l, g_w3l);

    // stage sizes: MB=1 -> 48KB x 4; MB=2 -> 64KB x 3 (both 192KB + 1KB ctrl)
    const int GSMEM = STG_OFF + 4 * (16384 + 32768);
    cudaFuncSetAttribute((const void*)gemm_bf16x3<0, 1, 4>,
                         cudaFuncAttributeMaxDynamicSharedMemorySize, GSMEM);
    cudaFuncSetAttribute((const void*)gemm_bf16x3<2, 1, 4>,
                         cudaFuncAttributeMaxDynamicSharedMemorySize, GSMEM);
    cudaFuncSetAttribute((const void*)gemm_bf16x3<3, 2, 3>,
                         cudaFuncAttributeMaxDynamicSharedMemorySize, GSMEM);

    dim3 tb(32, 8);

    // operand preparation: x split; weights transpose+split to K-major bf16
    split_bf16<<<2048, 256>>>(x, xh, xl, (size_t)M_TOTAL * D_DIM / 4);
    transpose_split_bf16<<<dim3(DI_DIM / 32, D_DIM / 32), tb>>>(W_in, w1h, w1l, D_DIM, DI_DIM);
    transpose_split_bf16<<<dim3(512 / 32, DI_DIM / 32), tb>>>(W_fwd, w2h, w2l, DI_DIM, 512);
    transpose_split_bf16<<<dim3(512 / 32, DI_DIM / 32), tb>>>(
        W_bwd, w2h + (size_t)512 * DI_DIM, w2l + (size_t)512 * DI_DIM, DI_DIM, 512);
    transpose_split_bf16<<<dim3(D_DIM / 32, 512 / 32), tb>>>(W_out, w3h, w3l, 512, D_DIM);

    // z = x @ W_in  (fp32 + bf16 hi/lo epilogue)       M=128/CTA, 128 CTAs
    gemm_bf16x3<0, 1, 4><<<dim3(1, M_TOTAL / 128), 256, GSMEM>>>(
        xh, xl, w1h, w1l, zp, zh, zl, nullptr, DI_DIM, D_DIM);

    // dg^T = act(z @ [W_fwd|W_bwd])^T
    gemm_bf16x3<2, 1, 4><<<dim3(4, M_TOTAL / 128), 256, GSMEM>>>(
        zh, zl, w2h, w2l, dgp, nullptr, nullptr, zp, 1024, DI_DIM);

    // bidirectional gated scans -> h^T
    scan_kernel<<<dim3(DI_DIM, 4, 2), 256>>>();

    // h^T -> h row-major bf16 hi/lo
    transpose_split_bf16<<<dim3(M_TOTAL / 32, 512 / 32), tb>>>(hp, hh, hl, 512, M_TOTAL);

    // y = h @ W_out + x      M=256/CTA (2 accumulators), grid (8, 64)
    gemm_bf16x3<3, 2, 3><<<dim3(8, M_TOTAL / 256), 256, GSMEM>>>(
        hh, hl, w3h, w3l, op, nullptr, nullptr, x, D_DIM, 512);

    // LayerNorm
    ln_kernel<<<M_TOTAL, 256>>>(gamma, beta, out);
}

// round 8
// speedup vs baseline: 4.1183x; 1.0291x over previous
#include <cuda_runtime.h>
#include <cuda_bf16.h>
#include <math.h>
#include <stdint.h>

#define M_TOTAL 16384
#define D_DIM   2048
#define DI_DIM  256
#define L_SEQ   4096
#define LN_EPS  1e-5f

// ---------------- scratch ----------------
__device__ float g_z  [(size_t)M_TOTAL * DI_DIM];     // z fp32 row-major (gating)
__device__ float g_dg [(size_t)1024 * M_TOTAL];       // dg^T
__device__ float g_h  [(size_t)512  * M_TOTAL];       // h^T fp32
__device__ float g_out[(size_t)M_TOTAL * D_DIM];      // y = out + x

__device__ __nv_bfloat16 g_xh [(size_t)M_TOTAL * D_DIM];
__device__ __nv_bfloat16 g_xl [(size_t)M_TOTAL * D_DIM];
__device__ __nv_bfloat16 g_zh [(size_t)M_TOTAL * DI_DIM];
__device__ __nv_bfloat16 g_zl [(size_t)M_TOTAL * DI_DIM];
__device__ __nv_bfloat16 g_hh [(size_t)M_TOTAL * 512];
__device__ __nv_bfloat16 g_hl [(size_t)M_TOTAL * 512];
__device__ __nv_bfloat16 g_w1h[(size_t)DI_DIM * D_DIM];
__device__ __nv_bfloat16 g_w1l[(size_t)DI_DIM * D_DIM];
__device__ __nv_bfloat16 g_w2h[(size_t)1024 * DI_DIM];
__device__ __nv_bfloat16 g_w2l[(size_t)1024 * DI_DIM];
__device__ __nv_bfloat16 g_w3h[(size_t)D_DIM * 512];
__device__ __nv_bfloat16 g_w3l[(size_t)D_DIM * 512];

// ---------------- arch feature gate ----------------
#if defined(__CUDA_ARCH_FEAT_SM103_ALL) || defined(__CUDA_ARCH_FEAT_SM100_ALL) || \
    defined(__CUDA_ARCH_FEAT_SM101_ALL) || defined(__CUDA_ARCH_SPECIFIC__)
#define TC_OK 1
#else
#define TC_OK 0
#endif

// ---------------- helpers ----------------
__device__ __forceinline__ uint32_t smem_u32(const void* p) {
    uint32_t a;
    asm("{ .reg .u64 t; cvta.to.shared.u64 t, %1; cvt.u32.u64 %0, t; }" : "=r"(a) : "l"(p));
    return a;
}

__device__ __forceinline__ float bf16hi(float a) {
    return __bfloat162float(__float2bfloat16_rn(a));
}
__device__ __forceinline__ uint32_t bf16pack(float a, float b) {
    __nv_bfloat162 t = __floats2bfloat162_rn(a, b);
    return *reinterpret_cast<uint32_t*>(&t);
}

#define CP_ASYNC16(dst, src) \
    asm volatile("cp.async.cg.shared.global [%0], [%1], 16;" :: "r"(dst), "l"(src))
// .noinc: arrive against the PRE-INITIALIZED count (default form is +1/-1 = net-zero
// and the barrier never completes -> R7 deadlock).
#define CP_ASYNC_ARRIVE_NOINC(mbar) \
    asm volatile("cp.async.mbarrier.arrive.noinc.shared::cta.b64 [%0];" :: "r"(mbar) : "memory")

#define MBARRIER_INIT(addr, cnt) \
    asm volatile("mbarrier.init.shared.b64 [%0], %1;" :: "r"(addr), "r"(cnt) : "memory")

__device__ __forceinline__ void mbar_wait(uint32_t mbar, uint32_t parity) {
    asm volatile(
        "{\n\t.reg .pred P;\n\t"
        "W0_%=:\n\t"
        "mbarrier.try_wait.parity.acquire.cta.shared::cta.b64 P, [%0], %1, 0x989680;\n\t"
        "@P bra W1_%=;\n\t"
        "bra W0_%=;\n\t"
        "W1_%=:\n\t}"
        :: "r"(mbar), "r"(parity) : "memory");
}

#define FENCE_ASYNC_SHARED() \
    asm volatile("fence.proxy.async.shared::cta;" ::: "memory")

#if TC_OK
#define TCGEN05_ALLOC(smem_res, ncols) \
    asm volatile("tcgen05.alloc.cta_group::1.sync.aligned.shared::cta.b32 [%0], %1;" \
                 :: "r"((uint32_t)(smem_res)), "r"((uint32_t)(ncols)) : "memory")
#define TCGEN05_DEALLOC(tmem, ncols) \
    asm volatile("tcgen05.dealloc.cta_group::1.sync.aligned.b32 %0, %1;" \
                 :: "r"(tmem), "r"((uint32_t)(ncols)))
#define TCGEN05_RELINQUISH() \
    asm volatile("tcgen05.relinquish_alloc_permit.cta_group::1.sync.aligned;")
#define TCGEN05_COMMIT(mbar) \
    asm volatile("tcgen05.commit.cta_group::1.mbarrier::arrive::one.shared::cluster.b64 [%0];" \
                 :: "r"((uint32_t)(mbar)) : "memory")
#define TCGEN05_FENCE_AFTER() \
    asm volatile("tcgen05.fence::after_thread_sync;" ::: "memory")
#define TCGEN05_WAIT_LD() \
    asm volatile("tcgen05.wait::ld.sync.aligned;" ::: "memory")

#define TCGEN05_LD_X32(r, tmem_addr) \
    asm volatile( \
        "tcgen05.ld.sync.aligned.32x32b.x32.b32 " \
        "{%0, %1, %2, %3, %4, %5, %6, %7, " \
        " %8, %9, %10, %11, %12, %13, %14, %15, " \
        " %16, %17, %18, %19, %20, %21, %22, %23, " \
        " %24, %25, %26, %27, %28, %29, %30, %31}, [%32];" \
        : "=r"((r)[0]),  "=r"((r)[1]),  "=r"((r)[2]),  "=r"((r)[3]), \
          "=r"((r)[4]),  "=r"((r)[5]),  "=r"((r)[6]),  "=r"((r)[7]), \
          "=r"((r)[8]),  "=r"((r)[9]),  "=r"((r)[10]), "=r"((r)[11]), \
          "=r"((r)[12]), "=r"((r)[13]), "=r"((r)[14]), "=r"((r)[15]), \
          "=r"((r)[16]), "=r"((r)[17]), "=r"((r)[18]), "=r"((r)[19]), \
          "=r"((r)[20]), "=r"((r)[21]), "=r"((r)[22]), "=r"((r)[23]), \
          "=r"((r)[24]), "=r"((r)[25]), "=r"((r)[26]), "=r"((r)[27]), \
          "=r"((r)[28]), "=r"((r)[29]), "=r"((r)[30]), "=r"((r)[31]) \
        : "r"(tmem_addr))

__device__ __forceinline__ void mma_bf16(uint32_t d, uint64_t ad, uint64_t bd,
                                         uint32_t idesc, uint32_t en) {
    asm volatile(
        "{\n\t.reg .pred p;\n\t"
        "setp.ne.u32 p, %5, 0;\n\t"
        "tcgen05.mma.cta_group::1.kind::f16 [%0], %1, %2, %3, {%4, %4, %4, %4}, p;\n\t}"
        :: "r"(d), "l"(ad), "l"(bd), "r"(idesc), "r"(0u), "r"(en) : "memory");
}
#else
#define TCGEN05_ALLOC(smem_res, ncols)  do {} while (0)
#define TCGEN05_DEALLOC(tmem, ncols)    do {} while (0)
#define TCGEN05_RELINQUISH()            do {} while (0)
#define TCGEN05_COMMIT(mbar)            do {} while (0)
#define TCGEN05_FENCE_AFTER()           do {} while (0)
#define TCGEN05_WAIT_LD()               do {} while (0)
#define TCGEN05_LD_X32(r, tmem_addr) \
    do { _Pragma("unroll") for (int _i = 0; _i < 32; _i++) (r)[_i] = 0u; } while (0)
__device__ __forceinline__ void mma_bf16(uint32_t, uint64_t, uint64_t, uint32_t, uint32_t) {}
#endif

// SW128 K-major SMEM descriptor (layout=2, ver=1, SBO=64, LBO=1)
__device__ __forceinline__ uint64_t sdesc(uint32_t addr) {
    return 0x4000404000010000ULL | (uint64_t)((addr >> 4) & 0x3FFF);
}

#define STG_OFF 1024
// idesc kind::f16 bf16: dtype=F32(1@4), atype=BF16(1@7), btype=BF16(1@10), N/8@17, M/16@24
#define IDESC_BF16 ((1u << 4) | (1u << 7) | (1u << 10) | ((256u / 8) << 17) | ((128u / 16) << 24))

// ---------------------------------------------------------------------------
// bf16x3 Ootomo GEMM, warp-specialized producer/consumer pipeline.
// BK=32 fp elems per chunk, hi|lo packed into 128B SW128 rows
// (hi bytes [0,64) -> desc +0/+2, lo bytes [64,128) -> desc +4/+6).
// Warps 0-6: cp.async producers; full[s] count=224, .noinc arrivals.
// Warp 7 lane 0: MMA consumer; tcgen05.commit arrives empty[s] (count 1).
// Tile (MB*128) x 256, MB TMEM accumulators, DEPTH stages.
// MODE 0: row-major fp32 + bf16 hi/lo split store (z producer)
// MODE 2: delta/gate epilogue, transposed store into dg^T (EX = z fp32)
// MODE 3: row-major store + residual EX
// ---------------------------------------------------------------------------
template<int MODE, int MB, int DEPTH>
__global__ void __launch_bounds__(256)
gemm_bf16x3(const __nv_bfloat16* __restrict__ Ah, const __nv_bfloat16* __restrict__ Al,
            const __nv_bfloat16* __restrict__ Bh, const __nv_bfloat16* __restrict__ Bl,
            float* __restrict__ C, __nv_bfloat16* __restrict__ Chi,
            __nv_bfloat16* __restrict__ Clo, const float* __restrict__ EX,
            int N, int K)
{
    constexpr int ABYTES = MB * 16384;      // A stage bytes (hi|lo packed rows)
    constexpr int STAGE  = ABYTES + 32768;  // + B (256 rows x 128B)
    constexpr int NCOLS  = MB * 256;
    constexpr int FULL_OFF  = 16;
    constexpr int EMPTY_OFF = 16 + 8 * DEPTH;

    extern __shared__ __align__(1024) char dsm[];
    uint32_t sb = smem_u32(dsm);
    int tid = threadIdx.x, wid = tid >> 5, lane = tid & 31;
    int n0 = blockIdx.x * 256, m0 = blockIdx.y * (MB * 128);

    if (wid == 0) TCGEN05_ALLOC(sb, NCOLS);
    if (tid == 0) {
#pragma unroll
        for (int s = 0; s < DEPTH; s++) {
            MBARRIER_INIT(sb + FULL_OFF  + 8 * s, 224);  // 7 producer warps x 32 threads
            MBARRIER_INIT(sb + EMPTY_OFF + 8 * s, 1);    // consumer commit
        }
    }
    __syncthreads();
    uint32_t tmem;
    asm volatile("ld.shared.b32 %0, [%1];" : "=r"(tmem) : "r"(sb));
    if (wid == 0) TCGEN05_RELINQUISH();

    const int NC = K >> 5;                  // 32-element K chunks (NC >= DEPTH everywhere)

    if (wid < 7) {
        // ---------------- producers ----------------
        for (int c = 0; c < NC; c++) {
            int st = c % DEPTH;
            if (c >= DEPTH)   // stage free once MMA round (c/DEPTH - 1) committed
                mbar_wait(sb + EMPTY_OFF + 8 * st, ((c / DEPTH) & 1) ^ 1u);
            int kc = c * 32;
            uint32_t sa = sb + STG_OFF + st * STAGE;
            for (int idx = tid; idx < MB * 1024; idx += 224) {   // A: MB*128 rows x 8 segs
                int r = idx >> 3, k8 = idx & 7;
                uint32_t byte = r * 128 + k8 * 16;
                uint32_t sw = byte ^ ((byte >> 3) & 0x70);
                const __nv_bfloat16* src = (k8 < 4) ? Ah : Al;
                CP_ASYNC16(sa + sw, (const void*)(src + (size_t)(m0 + r) * K + kc + (k8 & 3) * 8));
            }
            for (int idx = tid; idx < 2048; idx += 224) {        // B: 256 rows x 8 segs
                int r = idx >> 3, k8 = idx & 7;
                uint32_t byte = r * 128 + k8 * 16;
                uint32_t sw = byte ^ ((byte >> 3) & 0x70);
                const __nv_bfloat16* src = (k8 < 4) ? Bh : Bl;
                CP_ASYNC16(sa + ABYTES + sw, (const void*)(src + (size_t)(n0 + r) * K + kc + (k8 & 3) * 8));
            }
            CP_ASYNC_ARRIVE_NOINC(sb + FULL_OFF + 8 * st);
        }
    } else if (lane == 0) {
        // ---------------- consumer (warp 7 lane 0) ----------------
        for (int c = 0; c < NC; c++) {
            int st = c % DEPTH;
            mbar_wait(sb + FULL_OFF + 8 * st, (uint32_t)((c / DEPTH) & 1));
            FENCE_ASYNC_SHARED();
            uint32_t sa = sb + STG_OFF + st * STAGE;
            uint64_t bd = sdesc(sa + ABYTES);
#pragma unroll
            for (int mb = 0; mb < MB; mb++) {
                uint64_t ad = sdesc(sa + mb * 16384);
                uint32_t dt = tmem + mb * 256;
#pragma unroll
                for (int k = 0; k < 2; k++)              // hi*hi
                    mma_bf16(dt, ad + 2 * k, bd + 2 * k, IDESC_BF16, (uint32_t)((c | k) != 0));
#pragma unroll
                for (int k = 0; k < 2; k++)              // hi*lo
                    mma_bf16(dt, ad + 2 * k, bd + 4 + 2 * k, IDESC_BF16, 1u);
#pragma unroll
                for (int k = 0; k < 2; k++)              // lo*hi
                    mma_bf16(dt, ad + 4 + 2 * k, bd + 2 * k, IDESC_BF16, 1u);
            }
            TCGEN05_COMMIT(sb + EMPTY_OFF + 8 * st);
        }
        // final MMA completion (its empty arrival is never consumed by producers)
        mbar_wait(sb + EMPTY_OFF + 8 * ((NC - 1) % DEPTH), (uint32_t)(((NC - 1) / DEPTH) & 1));
    }

    __syncthreads();
    TCGEN05_FENCE_AFTER();

    // -------- epilogue --------
    int mrow, ccb, ccend;
    uint32_t tb;
    if constexpr (MB == 2) {        // warp w -> rows (w&3)*32 + (w>>2)*128, all 256 cols
        mrow = (wid & 3) * 32 + lane + (wid >> 2) * 128;
        ccb = 0; ccend = 256;
        tb = tmem + (wid >> 2) * 256;
    } else {                        // warp w -> rows (w&3)*32, col half (w>>2)*128
        mrow = (wid & 3) * 32 + lane;
        ccb = (wid >> 2) * 128; ccend = ccb + 128;
        tb = tmem;
    }
    int m = m0 + mrow;
    uint32_t regs[32];
#pragma unroll
    for (int cc = ccb; cc < ccend; cc += 32) {
        TCGEN05_LD_X32(regs, tb + cc);
        TCGEN05_WAIT_LD();

        if (MODE == 0) {
#pragma unroll
            for (int j = 0; j < 32; j += 4) {
                size_t off = (size_t)m * N + n0 + cc + j;
                float4 v = make_float4(__uint_as_float(regs[j]),
                                       __uint_as_float(regs[j + 1]),
                                       __uint_as_float(regs[j + 2]),
                                       __uint_as_float(regs[j + 3]));
                *(float4*)&C[off] = v;
                float hx = bf16hi(v.x), hy = bf16hi(v.y), hz = bf16hi(v.z), hw = bf16hi(v.w);
                *(uint2*)&Chi[off] = make_uint2(bf16pack(v.x, v.y), bf16pack(v.z, v.w));
                *(uint2*)&Clo[off] = make_uint2(bf16pack(v.x - hx, v.y - hy),
                                                bf16pack(v.z - hz, v.w - hw));
            }
        } else if (MODE == 3) {
#pragma unroll
            for (int j = 0; j < 32; j += 4) {
                size_t off = (size_t)m * N + n0 + cc + j;
                float4 v = make_float4(__uint_as_float(regs[j]),
                                       __uint_as_float(regs[j + 1]),
                                       __uint_as_float(regs[j + 2]),
                                       __uint_as_float(regs[j + 3]));
                float4 r4 = *(const float4*)&EX[off];
                v.x += r4.x; v.y += r4.y; v.z += r4.z; v.w += r4.w;
                *(float4*)&C[off] = v;
            }
        } else {  // MODE 2: delta/gate, transposed store into dg^T
            int jj0 = (n0 + cc) & 511;
            if (jj0 < 256) {
#pragma unroll
                for (int j = 0; j < 32; j++) {
                    float v = __uint_as_float(regs[j]);
                    v = 1.f / (1.f + expf(-v));
                    C[(size_t)(n0 + cc + j) * M_TOTAL + m] = v;
                }
            } else {
                int ch0 = jj0 - 256;
#pragma unroll
                for (int j = 0; j < 32; j += 4) {
                    float4 zv = *(const float4*)&EX[(size_t)m * DI_DIM + ch0 + j];
                    C[(size_t)(n0 + cc + j + 0) * M_TOTAL + m] = __uint_as_float(regs[j + 0]) * zv.x;
                    C[(size_t)(n0 + cc + j + 1) * M_TOTAL + m] = __uint_as_float(regs[j + 1]) * zv.y;
                    C[(size_t)(n0 + cc + j + 2) * M_TOTAL + m] = __uint_as_float(regs[j + 2]) * zv.z;
                    C[(size_t)(n0 + cc + j + 3) * M_TOTAL + m] = __uint_as_float(regs[j + 3]) * zv.w;
                }
            }
        }
    }

    __syncthreads();
    if (wid == 0) TCGEN05_DEALLOC(tmem, NCOLS);
}

// ---------------------------------------------------------------------------
// elementwise bf16 hi/lo split: fp32 -> (hi, lo)
// ---------------------------------------------------------------------------
__global__ void __launch_bounds__(256)
split_bf16(const float* __restrict__ in, __nv_bfloat16* __restrict__ ohi,
           __nv_bfloat16* __restrict__ olo, size_t n4)
{
    size_t i = (size_t)blockIdx.x * blockDim.x + threadIdx.x;
    size_t stride = (size_t)gridDim.x * blockDim.x;
    for (; i < n4; i += stride) {
        float4 v = ((const float4*)in)[i];
        float hx = bf16hi(v.x), hy = bf16hi(v.y), hz = bf16hi(v.z), hw = bf16hi(v.w);
        ((uint2*)ohi)[i] = make_uint2(bf16pack(v.x, v.y), bf16pack(v.z, v.w));
        ((uint2*)olo)[i] = make_uint2(bf16pack(v.x - hx, v.y - hy),
                                      bf16pack(v.z - hz, v.w - hw));
    }
}

// ---------------------------------------------------------------------------
// merged weight prep: all 4 transpose+split jobs in one launch.
// ---------------------------------------------------------------------------
__global__ void __launch_bounds__(256)
weights_prep(const float* __restrict__ W_in, const float* __restrict__ W_fwd,
             const float* __restrict__ W_bwd, const float* __restrict__ W_out,
             __nv_bfloat16* __restrict__ w1h, __nv_bfloat16* __restrict__ w1l,
             __nv_bfloat16* __restrict__ w2h, __nv_bfloat16* __restrict__ w2l,
             __nv_bfloat16* __restrict__ w3h, __nv_bfloat16* __restrict__ w3l)
{
    int id = blockIdx.x;
    const float* in;
    __nv_bfloat16 *oh, *ol;
    int R, C, bx, by;
    if (id < 512)       { in = W_in;  oh = w1h; ol = w1l; R = D_DIM;  C = DI_DIM; bx = id & 7;  by = id >> 3; }
    else if (id < 640)  { id -= 512; in = W_fwd; oh = w2h; ol = w2l; R = DI_DIM; C = 512; bx = id & 15; by = id >> 4; }
    else if (id < 768)  { id -= 640; in = W_bwd; oh = w2h + (size_t)512 * DI_DIM;
                          ol = w2l + (size_t)512 * DI_DIM; R = DI_DIM; C = 512; bx = id & 15; by = id >> 4; }
    else                { id -= 768; in = W_out; oh = w3h; ol = w3l; R = 512; C = D_DIM; bx = id & 63; by = id >> 6; }

    __shared__ float t[32][33];
    int c0 = bx * 32, r0 = by * 32;
    int tx = threadIdx.x & 31, ty = threadIdx.x >> 5;
#pragma unroll
    for (int i = 0; i < 32; i += 8)
        t[ty + i][tx] = in[(size_t)(r0 + ty + i) * C + c0 + tx];
    __syncthreads();
#pragma unroll
    for (int i = 0; i < 32; i += 8) {
        float v = t[tx][ty + i];
        float h = bf16hi(v);
        size_t off = (size_t)(c0 + ty + i) * R + r0 + tx;
        oh[off] = __float2bfloat16_rn(v);
        ol[off] = __float2bfloat16_rn(v - h);
    }
}

// ---------------------------------------------------------------------------
// 32x32 tiled transpose + bf16 split: in[R][C] fp32 -> hi/lo bf16 [C][R]
// ---------------------------------------------------------------------------
__global__ void __launch_bounds__(256)
transpose_split_bf16(const float* __restrict__ in, __nv_bfloat16* __restrict__ oh,
                     __nv_bfloat16* __restrict__ ol, int R, int C)
{
    __shared__ float t[32][33];
    int c0 = blockIdx.x * 32, r0 = blockIdx.y * 32;
    int tx = threadIdx.x, ty = threadIdx.y;
#pragma unroll
    for (int i = 0; i < 32; i += 8)
        t[ty + i][tx] = in[(size_t)(r0 + ty + i) * C + c0 + tx];
    __syncthreads();
#pragma unroll
    for (int i = 0; i < 32; i += 8) {
        float v = t[tx][ty + i];
        float h = bf16hi(v);
        size_t off = (size_t)(c0 + ty + i) * R + r0 + tx;
        oh[off] = __float2bfloat16_rn(v);
        ol[off] = __float2bfloat16_rn(v - h);
    }
}

// ---------------------------------------------------------------------------
// Gated linear scan: block per (channel, batch, dir)
// ---------------------------------------------------------------------------
__global__ __launch_bounds__(256)
void scan_kernel()
{
    int d = blockIdx.x, bb = blockIdx.y, dir = blockIdx.z;
    const float* dptr = &g_dg[(size_t)(dir * 512 + d)       * M_TOTAL + bb * L_SEQ];
    const float* gptr = &g_dg[(size_t)(dir * 512 + 256 + d) * M_TOTAL + bb * L_SEQ];
    float*       hptr = &g_h [(size_t)(dir * 256 + d)       * M_TOTAL + bb * L_SEQ];

    int tid = threadIdx.x;
    int base = (dir == 0) ? tid * 16 : (L_SEQ - 16 * (tid + 1));

    float tmpd[16], tmpg[16];
#pragma unroll
    for (int q = 0; q < 4; q++) {
        *(float4*)&tmpd[q * 4] = *(const float4*)&dptr[base + q * 4];
        *(float4*)&tmpg[q * 4] = *(const float4*)&gptr[base + q * 4];
    }
    float dl[16], gt[16];
#pragma unroll
    for (int e = 0; e < 16; e++) {
        int src = (dir == 0) ? e : (15 - e);
        dl[e] = tmpd[src];
        gt[e] = tmpg[src];
    }

    float Aseg = 1.f, Bseg = 0.f;
#pragma unroll
    for (int e = 0; e < 16; e++) {
        Aseg = Aseg * dl[e];
        Bseg = fmaf(Bseg, dl[e], gt[e]);
    }

    __shared__ float sA[256], sB[256];
    sA[tid] = Aseg; sB[tid] = Bseg;
    __syncthreads();
#pragma unroll
    for (int off = 1; off < 256; off <<= 1) {
        float pA = 0.f, pB = 0.f;
        bool has = (tid >= off);
        if (has) { pA = sA[tid - off]; pB = sB[tid - off]; }
        __syncthreads();
        if (has) {
            float Ac = sA[tid], Bc = sB[tid];
            sA[tid] = Ac * pA;
            sB[tid] = fmaf(Ac, pB, Bc);
        }
        __syncthreads();
    }

    float h = (tid == 0) ? 0.f : sB[tid - 1];
    float hv[16];
#pragma unroll
    for (int e = 0; e < 16; e++) {
        h = fmaf(h, dl[e], gt[e]);
        hv[e] = h;
    }

    float outv[16];
#pragma unroll
    for (int q = 0; q < 16; q++)
        outv[q] = (dir == 0) ? hv[q] : hv[15 - q];
#pragma unroll
    for (int q = 0; q < 4; q++)
        *(float4*)&hptr[base + q * 4] =
            make_float4(outv[q * 4], outv[q * 4 + 1], outv[q * 4 + 2], outv[q * 4 + 3]);
}

// ---------------------------------------------------------------------------
// LayerNorm over D=2048 per row
// ---------------------------------------------------------------------------
__global__ __launch_bounds__(256)
void ln_kernel(const float* __restrict__ gamma, const float* __restrict__ beta,
               float* __restrict__ out)
{
    int row = blockIdx.x;
    int tid = threadIdx.x;
    const float* yrow = &g_out[(size_t)row * D_DIM];

    float v[8];
    *(float4*)&v[0] = *(const float4*)&yrow[tid * 8];
    *(float4*)&v[4] = *(const float4*)&yrow[tid * 8 + 4];

    float s = 0.f, s2 = 0.f;
#pragma unroll
    for (int e = 0; e < 8; e++) { s += v[e]; s2 = fmaf(v[e], v[e], s2); }

#pragma unroll
    for (int o = 16; o > 0; o >>= 1) {
        s  += __shfl_xor_sync(0xffffffffu, s,  o);
        s2 += __shfl_xor_sync(0xffffffffu, s2, o);
    }
    __shared__ float sh[16];
    int w = tid >> 5, lane = tid & 31;
    if (lane == 0) { sh[w] = s; sh[8 + w] = s2; }
    __syncthreads();
    float S = 0.f, S2 = 0.f;
    if (lane < 8) { S = sh[lane]; S2 = sh[8 + lane]; }
#pragma unroll
    for (int o = 4; o > 0; o >>= 1) {
        S  += __shfl_xor_sync(0xffffffffu, S,  o);
        S2 += __shfl_xor_sync(0xffffffffu, S2, o);
    }
    S  = __shfl_sync(0xffffffffu, S,  0);
    S2 = __shfl_sync(0xffffffffu, S2, 0);

    const float invD = 1.f / (float)D_DIM;
    float mu = S * invD;
    float var = fmaf(S2, invD, -mu * mu);
    float inv = rsqrtf(var + LN_EPS);

    float g[8], be[8];
    *(float4*)&g[0]  = *(const float4*)&gamma[tid * 8];
    *(float4*)&g[4]  = *(const float4*)&gamma[tid * 8 + 4];
    *(float4*)&be[0] = *(const float4*)&beta[tid * 8];
    *(float4*)&be[4] = *(const float4*)&beta[tid * 8 + 4];

    float r[8];
#pragma unroll
    for (int e = 0; e < 8; e++)
        r[e] = fmaf((v[e] - mu) * inv, g[e], be[e]);

    float* orow = &out[(size_t)row * D_DIM];
    *(float4*)&orow[tid * 8]     = make_float4(r[0], r[1], r[2], r[3]);
    *(float4*)&orow[tid * 8 + 4] = make_float4(r[4], r[5], r[6], r[7]);
}

// ---------------------------------------------------------------------------
extern "C" void kernel_launch(void* const* d_in, const int* in_sizes, int n_in,
                              void* d_out, int out_size)
{
    const float* x     = (const float*)d_in[0];
    const float* W_in  = (const float*)d_in[1];
    const float* W_fwd = (const float*)d_in[2];
    const float* W_bwd = (const float*)d_in[3];
    const float* W_out = (const float*)d_in[4];
    const float* gamma = (const float*)d_in[5];
    const float* beta  = (const float*)d_in[6];
    float* out = (float*)d_out;

    float *zp, *dgp, *hp, *op;
    __nv_bfloat16 *xh, *xl, *zh, *zl, *hh, *hl, *w1h, *w1l, *w2h, *w2l, *w3h, *w3l;
    cudaGetSymbolAddress((void**)&zp,  g_z);
    cudaGetSymbolAddress((void**)&dgp, g_dg);
    cudaGetSymbolAddress((void**)&hp,  g_h);
    cudaGetSymbolAddress((void**)&op,  g_out);
    cudaGetSymbolAddress((void**)&xh,  g_xh);
    cudaGetSymbolAddress((void**)&xl,  g_xl);
    cudaGetSymbolAddress((void**)&zh,  g_zh);
    cudaGetSymbolAddress((void**)&zl,  g_zl);
    cudaGetSymbolAddress((void**)&hh,  g_hh);
    cudaGetSymbolAddress((void**)&hl,  g_hl);
    cudaGetSymbolAddress((void**)&w1h, g_w1h);
    cudaGetSymbolAddress((void**)&w1l, g_w1l);
    cudaGetSymbolAddress((void**)&w2h, g_w2h);
    cudaGetSymbolAddress((void**)&w2l, g_w2l);
    cudaGetSymbolAddress((void**)&w3h, g_w3h);
    cudaGetSymbolAddress((void**)&w3l, g_w3l);

    // stage sizes: MB=1 -> 48KB x 4; MB=2 -> 64KB x 3 (both 192KB + 1KB ctrl)
    const int GSMEM = STG_OFF + 4 * (16384 + 32768);
    cudaFuncSetAttribute((const void*)gemm_bf16x3<0, 1, 4>,
                         cudaFuncAttributeMaxDynamicSharedMemorySize, GSMEM);
    cudaFuncSetAttribute((const void*)gemm_bf16x3<2, 1, 4>,
                         cudaFuncAttributeMaxDynamicSharedMemorySize, GSMEM);
    cudaFuncSetAttribute((const void*)gemm_bf16x3<3, 2, 3>,
                         cudaFuncAttributeMaxDynamicSharedMemorySize, GSMEM);

    // operand preparation
    split_bf16<<<2048, 256>>>(x, xh, xl, (size_t)M_TOTAL * D_DIM / 4);
    weights_prep<<<1792, 256>>>(W_in, W_fwd, W_bwd, W_out,
                                w1h, w1l, w2h, w2l, w3h, w3l);

    // z = x @ W_in  (fp32 + bf16 hi/lo epilogue)       M=128/CTA, 128 CTAs
    gemm_bf16x3<0, 1, 4><<<dim3(1, M_TOTAL / 128), 256, GSMEM>>>(
        xh, xl, w1h, w1l, zp, zh, zl, nullptr, DI_DIM, D_DIM);

    // dg^T = act(z @ [W_fwd|W_bwd])^T
    gemm_bf16x3<2, 1, 4><<<dim3(4, M_TOTAL / 128), 256, GSMEM>>>(
        zh, zl, w2h, w2l, dgp, nullptr, nullptr, zp, 1024, DI_DIM);

    // bidirectional gated scans -> h^T
    scan_kernel<<<dim3(DI_DIM, 4, 2), 256>>>();

    // h^T -> h row-major bf16 hi/lo
    transpose_split_bf16<<<dim3(M_TOTAL / 32, 512 / 32), dim3(32, 8)>>>(hp, hh, hl, 512, M_TOTAL);

    // y = h @ W_out + x      M=256/CTA (2 accumulators), grid (8, 64)
    gemm_bf16x3<3, 2, 3><<<dim3(8, M_TOTAL / 256), 256, GSMEM>>>(
        hh, hl, w3h, w3l, op, nullptr, nullptr, x, D_DIM, 512);

    // LayerNorm
    ln_kernel<<<M_TOTAL, 256>>>(gamma, beta, out);
}

// round 9
// speedup vs baseline: 4.2038x; 1.0208x over previous
#include <cuda_runtime.h>
#include <cuda_bf16.h>
#include <math.h>
#include <stdint.h>

#define M_TOTAL 16384
#define D_DIM   2048
#define DI_DIM  256
#define L_SEQ   4096
#define LN_EPS  1e-5f

// ---------------- scratch ----------------
__device__ float g_z  [(size_t)M_TOTAL * DI_DIM];     // z fp32 row-major (gating)
__device__ float g_dg [(size_t)1024 * M_TOTAL];       // dg^T
__device__ float g_h  [(size_t)512  * M_TOTAL];       // h^T fp32
__device__ float g_out[(size_t)M_TOTAL * D_DIM];      // y = out + x

__device__ __nv_bfloat16 g_xh [(size_t)M_TOTAL * D_DIM];
__device__ __nv_bfloat16 g_xl [(size_t)M_TOTAL * D_DIM];
__device__ __nv_bfloat16 g_zh [(size_t)M_TOTAL * DI_DIM];
__device__ __nv_bfloat16 g_zl [(size_t)M_TOTAL * DI_DIM];
__device__ __nv_bfloat16 g_hh [(size_t)M_TOTAL * 512];
__device__ __nv_bfloat16 g_hl [(size_t)M_TOTAL * 512];
__device__ __nv_bfloat16 g_w1h[(size_t)DI_DIM * D_DIM];
__device__ __nv_bfloat16 g_w1l[(size_t)DI_DIM * D_DIM];
__device__ __nv_bfloat16 g_w2h[(size_t)1024 * DI_DIM];
__device__ __nv_bfloat16 g_w2l[(size_t)1024 * DI_DIM];
__device__ __nv_bfloat16 g_w3h[(size_t)D_DIM * 512];
__device__ __nv_bfloat16 g_w3l[(size_t)D_DIM * 512];

// ---------------- arch feature gate ----------------
#if defined(__CUDA_ARCH_FEAT_SM103_ALL) || defined(__CUDA_ARCH_FEAT_SM100_ALL) || \
    defined(__CUDA_ARCH_FEAT_SM101_ALL) || defined(__CUDA_ARCH_SPECIFIC__)
#define TC_OK 1
#else
#define TC_OK 0
#endif

// ---------------- helpers ----------------
__device__ __forceinline__ uint32_t smem_u32(const void* p) {
    uint32_t a;
    asm("{ .reg .u64 t; cvta.to.shared.u64 t, %1; cvt.u32.u64 %0, t; }" : "=r"(a) : "l"(p));
    return a;
}

__device__ __forceinline__ float bf16hi(float a) {
    return __bfloat162float(__float2bfloat16_rn(a));
}
__device__ __forceinline__ uint32_t bf16pack(float a, float b) {
    __nv_bfloat162 t = __floats2bfloat162_rn(a, b);
    return *reinterpret_cast<uint32_t*>(&t);
}

#define CP_ASYNC16(dst, src) \
    asm volatile("cp.async.cg.shared.global [%0], [%1], 16;" :: "r"(dst), "l"(src))
// .noinc: arrive against the PRE-INITIALIZED count (default form is +1/-1 = net-zero).
#define CP_ASYNC_ARRIVE_NOINC(mbar) \
    asm volatile("cp.async.mbarrier.arrive.noinc.shared::cta.b64 [%0];" :: "r"(mbar) : "memory")

#define MBARRIER_INIT(addr, cnt) \
    asm volatile("mbarrier.init.shared.b64 [%0], %1;" :: "r"(addr), "r"(cnt) : "memory")

__device__ __forceinline__ void mbar_wait(uint32_t mbar, uint32_t parity) {
    asm volatile(
        "{\n\t.reg .pred P;\n\t"
        "W0_%=:\n\t"
        "mbarrier.try_wait.parity.acquire.cta.shared::cta.b64 P, [%0], %1, 0x989680;\n\t"
        "@P bra W1_%=;\n\t"
        "bra W0_%=;\n\t"
        "W1_%=:\n\t}"
        :: "r"(mbar), "r"(parity) : "memory");
}

#define FENCE_ASYNC_SHARED() \
    asm volatile("fence.proxy.async.shared::cta;" ::: "memory")

#if TC_OK
#define TCGEN05_ALLOC(smem_res, ncols) \
    asm volatile("tcgen05.alloc.cta_group::1.sync.aligned.shared::cta.b32 [%0], %1;" \
                 :: "r"((uint32_t)(smem_res)), "r"((uint32_t)(ncols)) : "memory")
#define TCGEN05_DEALLOC(tmem, ncols) \
    asm volatile("tcgen05.dealloc.cta_group::1.sync.aligned.b32 %0, %1;" \
                 :: "r"(tmem), "r"((uint32_t)(ncols)))
#define TCGEN05_RELINQUISH() \
    asm volatile("tcgen05.relinquish_alloc_permit.cta_group::1.sync.aligned;")
#define TCGEN05_COMMIT(mbar) \
    asm volatile("tcgen05.commit.cta_group::1.mbarrier::arrive::one.shared::cluster.b64 [%0];" \
                 :: "r"((uint32_t)(mbar)) : "memory")
#define TCGEN05_FENCE_AFTER() \
    asm volatile("tcgen05.fence::after_thread_sync;" ::: "memory")
#define TCGEN05_WAIT_LD() \
    asm volatile("tcgen05.wait::ld.sync.aligned;" ::: "memory")

#define TCGEN05_LD_X32(r, tmem_addr) \
    asm volatile( \
        "tcgen05.ld.sync.aligned.32x32b.x32.b32 " \
        "{%0, %1, %2, %3, %4, %5, %6, %7, " \
        " %8, %9, %10, %11, %12, %13, %14, %15, " \
        " %16, %17, %18, %19, %20, %21, %22, %23, " \
        " %24, %25, %26, %27, %28, %29, %30, %31}, [%32];" \
        : "=r"((r)[0]),  "=r"((r)[1]),  "=r"((r)[2]),  "=r"((r)[3]), \
          "=r"((r)[4]),  "=r"((r)[5]),  "=r"((r)[6]),  "=r"((r)[7]), \
          "=r"((r)[8]),  "=r"((r)[9]),  "=r"((r)[10]), "=r"((r)[11]), \
          "=r"((r)[12]), "=r"((r)[13]), "=r"((r)[14]), "=r"((r)[15]), \
          "=r"((r)[16]), "=r"((r)[17]), "=r"((r)[18]), "=r"((r)[19]), \
          "=r"((r)[20]), "=r"((r)[21]), "=r"((r)[22]), "=r"((r)[23]), \
          "=r"((r)[24]), "=r"((r)[25]), "=r"((r)[26]), "=r"((r)[27]), \
          "=r"((r)[28]), "=r"((r)[29]), "=r"((r)[30]), "=r"((r)[31]) \
        : "r"(tmem_addr))

__device__ __forceinline__ void mma_bf16(uint32_t d, uint64_t ad, uint64_t bd,
                                         uint32_t idesc, uint32_t en) {
    asm volatile(
        "{\n\t.reg .pred p;\n\t"
        "setp.ne.u32 p, %5, 0;\n\t"
        "tcgen05.mma.cta_group::1.kind::f16 [%0], %1, %2, %3, {%4, %4, %4, %4}, p;\n\t}"
        :: "r"(d), "l"(ad), "l"(bd), "r"(idesc), "r"(0u), "r"(en) : "memory");
}
#else
#define TCGEN05_ALLOC(smem_res, ncols)  do {} while (0)
#define TCGEN05_DEALLOC(tmem, ncols)    do {} while (0)
#define TCGEN05_RELINQUISH()            do {} while (0)
#define TCGEN05_COMMIT(mbar)            do {} while (0)
#define TCGEN05_FENCE_AFTER()           do {} while (0)
#define TCGEN05_WAIT_LD()               do {} while (0)
#define TCGEN05_LD_X32(r, tmem_addr) \
    do { _Pragma("unroll") for (int _i = 0; _i < 32; _i++) (r)[_i] = 0u; } while (0)
__device__ __forceinline__ void mma_bf16(uint32_t, uint64_t, uint64_t, uint32_t, uint32_t) {}
#endif

// SW128 K-major SMEM descriptor (layout=2, ver=1, SBO=64, LBO=1)
__device__ __forceinline__ uint64_t sdesc(uint32_t addr) {
    return 0x4000404000010000ULL | (uint64_t)((addr >> 4) & 0x3FFF);
}

#define STG_OFF  1024
#define STAGE_SZ 49152                       // A 16K (hi|lo packed) + B 32K
#define DEPTH    2
#define GSMEM    (STG_OFF + DEPTH * STAGE_SZ)  // 99,328 B -> 2 CTAs/SM

// idesc kind::f16 bf16: dtype=F32(1@4), atype=BF16(1@7), btype=BF16(1@10), N/8@17, M/16@24
#define IDESC_BF16 ((1u << 4) | (1u << 7) | (1u << 10) | ((256u / 8) << 17) | ((128u / 16) << 24))

// ---------------------------------------------------------------------------
// bf16x3 Ootomo GEMM, warp-specialized producer/consumer, 2 CTAs/SM.
// BK=32 fp elems/chunk; hi|lo packed into 128B SW128 rows
// (hi bytes [0,64) -> desc +0/+2, lo bytes [64,128) -> desc +4/+6).
// Warps 0-6: cp.async producers; full[s] count=224, .noinc arrivals.
// Warp 7 lane 0: MMA consumer; tcgen05.commit arrives empty[s] (count 1).
// Tile 128 x 256, 256-col TMEM accumulator, DEPTH=2 stages (48KB each).
// Epilogue double-buffers LDTM against stores.
// MODE 0: row-major fp32 + bf16 hi/lo split store (z producer)
// MODE 2: delta/gate epilogue, transposed store into dg^T (EX = z fp32)
// MODE 3: row-major store + residual EX
// ---------------------------------------------------------------------------
template<int MODE>
__global__ void __launch_bounds__(256, 2)
gemm_bf16x3(const __nv_bfloat16* __restrict__ Ah, const __nv_bfloat16* __restrict__ Al,
            const __nv_bfloat16* __restrict__ Bh, const __nv_bfloat16* __restrict__ Bl,
            float* __restrict__ C, __nv_bfloat16* __restrict__ Chi,
            __nv_bfloat16* __restrict__ Clo, const float* __restrict__ EX,
            int N, int K)
{
    constexpr int FULL_OFF  = 16;
    constexpr int EMPTY_OFF = 16 + 8 * DEPTH;

    extern __shared__ __align__(1024) char dsm[];
    uint32_t sb = smem_u32(dsm);
    int tid = threadIdx.x, wid = tid >> 5, lane = tid & 31;
    int n0 = blockIdx.x * 256, m0 = blockIdx.y * 128;

    if (wid == 0) TCGEN05_ALLOC(sb, 256);
    if (tid == 0) {
#pragma unroll
        for (int s = 0; s < DEPTH; s++) {
            MBARRIER_INIT(sb + FULL_OFF  + 8 * s, 224);  // 7 producer warps x 32 threads
            MBARRIER_INIT(sb + EMPTY_OFF + 8 * s, 1);    // consumer commit
        }
    }
    __syncthreads();
    uint32_t tmem;
    asm volatile("ld.shared.b32 %0, [%1];" : "=r"(tmem) : "r"(sb));
    if (wid == 0) TCGEN05_RELINQUISH();

    const int NC = K >> 5;                  // 32-element K chunks (NC >= DEPTH everywhere)

    if (wid < 7) {
        // ---------------- producers ----------------
        for (int c = 0; c < NC; c++) {
            int st = c % DEPTH;
            if (c >= DEPTH)   // stage free once MMA round (c/DEPTH - 1) committed
                mbar_wait(sb + EMPTY_OFF + 8 * st, ((c / DEPTH) & 1) ^ 1u);
            int kc = c * 32;
            uint32_t sa = sb + STG_OFF + st * STAGE_SZ;
            for (int idx = tid; idx < 1024; idx += 224) {        // A: 128 rows x 8 segs
                int r = idx >> 3, k8 = idx & 7;
                uint32_t byte = r * 128 + k8 * 16;
                uint32_t sw = byte ^ ((byte >> 3) & 0x70);
                const __nv_bfloat16* src = (k8 < 4) ? Ah : Al;
                CP_ASYNC16(sa + sw, (const void*)(src + (size_t)(m0 + r) * K + kc + (k8 & 3) * 8));
            }
            for (int idx = tid; idx < 2048; idx += 224) {        // B: 256 rows x 8 segs
                int r = idx >> 3, k8 = idx & 7;
                uint32_t byte = r * 128 + k8 * 16;
                uint32_t sw = byte ^ ((byte >> 3) & 0x70);
                const __nv_bfloat16* src = (k8 < 4) ? Bh : Bl;
                CP_ASYNC16(sa + 16384 + sw, (const void*)(src + (size_t)(n0 + r) * K + kc + (k8 & 3) * 8));
            }
            CP_ASYNC_ARRIVE_NOINC(sb + FULL_OFF + 8 * st);
        }
    } else if (lane == 0) {
        // ---------------- consumer (warp 7 lane 0) ----------------
        for (int c = 0; c < NC; c++) {
            int st = c % DEPTH;
            mbar_wait(sb + FULL_OFF + 8 * st, (uint32_t)((c / DEPTH) & 1));
            FENCE_ASYNC_SHARED();
            uint32_t sa = sb + STG_OFF + st * STAGE_SZ;
            uint64_t ad = sdesc(sa);
            uint64_t bd = sdesc(sa + 16384);
#pragma unroll
            for (int k = 0; k < 2; k++)              // hi*hi
                mma_bf16(tmem, ad + 2 * k, bd + 2 * k, IDESC_BF16, (uint32_t)((c | k) != 0));
#pragma unroll
            for (int k = 0; k < 2; k++)              // hi*lo
                mma_bf16(tmem, ad + 2 * k, bd + 4 + 2 * k, IDESC_BF16, 1u);
#pragma unroll
            for (int k = 0; k < 2; k++)              // lo*hi
                mma_bf16(tmem, ad + 4 + 2 * k, bd + 2 * k, IDESC_BF16, 1u);
            TCGEN05_COMMIT(sb + EMPTY_OFF + 8 * st);
        }
        // final MMA completion (its empty arrival is never consumed by producers)
        mbar_wait(sb + EMPTY_OFF + 8 * ((NC - 1) % DEPTH), (uint32_t)(((NC - 1) / DEPTH) & 1));
    }

    __syncthreads();
    TCGEN05_FENCE_AFTER();

    // -------- epilogue: warp w -> rows (w&3)*32, col half (w>>2)*128 --------
    // LDTM double-buffered against the stores.
    int m = m0 + (wid & 3) * 32 + lane;
    int ccb = (wid >> 2) * 128;
    uint32_t ra[32], rb[32];

    TCGEN05_LD_X32(ra, tmem + ccb);
#pragma unroll
    for (int i = 0; i < 4; i++) {
        int cc = ccb + i * 32;
        uint32_t* cur = (i & 1) ? rb : ra;
        uint32_t* nxt = (i & 1) ? ra : rb;
        TCGEN05_WAIT_LD();                       // cur ready
        if (i < 3) TCGEN05_LD_X32(nxt, tmem + cc + 32);  // prefetch next (async)

        if (MODE == 0) {
#pragma unroll
            for (int j = 0; j < 32; j += 4) {
                size_t off = (size_t)m * N + n0 + cc + j;
                float4 v = make_float4(__uint_as_float(cur[j]),
                                       __uint_as_float(cur[j + 1]),
                                       __uint_as_float(cur[j + 2]),
                                       __uint_as_float(cur[j + 3]));
                *(float4*)&C[off] = v;
                float hx = bf16hi(v.x), hy = bf16hi(v.y), hz = bf16hi(v.z), hw = bf16hi(v.w);
                *(uint2*)&Chi[off] = make_uint2(bf16pack(v.x, v.y), bf16pack(v.z, v.w));
                *(uint2*)&Clo[off] = make_uint2(bf16pack(v.x - hx, v.y - hy),
                                                bf16pack(v.z - hz, v.w - hw));
            }
        } else if (MODE == 3) {
#pragma unroll
            for (int j = 0; j < 32; j += 4) {
                size_t off = (size_t)m * N + n0 + cc + j;
                float4 v = make_float4(__uint_as_float(cur[j]),
                                       __uint_as_float(cur[j + 1]),
                                       __uint_as_float(cur[j + 2]),
                                       __uint_as_float(cur[j + 3]));
                float4 r4 = *(const float4*)&EX[off];
                v.x += r4.x; v.y += r4.y; v.z += r4.z; v.w += r4.w;
                *(float4*)&C[off] = v;
            }
        } else {  // MODE 2: delta/gate, transposed store into dg^T
            int jj0 = (n0 + cc) & 511;
            if (jj0 < 256) {
#pragma unroll
                for (int j = 0; j < 32; j++) {
                    float v = __uint_as_float(cur[j]);
                    v = 1.f / (1.f + __expf(-v));
                    C[(size_t)(n0 + cc + j) * M_TOTAL + m] = v;
                }
            } else {
                int ch0 = jj0 - 256;
#pragma unroll
                for (int j = 0; j < 32; j += 4) {
                    float4 zv = *(const float4*)&EX[(size_t)m * DI_DIM + ch0 + j];
                    C[(size_t)(n0 + cc + j + 0) * M_TOTAL + m] = __uint_as_float(cur[j + 0]) * zv.x;
                    C[(size_t)(n0 + cc + j + 1) * M_TOTAL + m] = __uint_as_float(cur[j + 1]) * zv.y;
                    C[(size_t)(n0 + cc + j + 2) * M_TOTAL + m] = __uint_as_float(cur[j + 2]) * zv.z;
                    C[(size_t)(n0 + cc + j + 3) * M_TOTAL + m] = __uint_as_float(cur[j + 3]) * zv.w;
                }
            }
        }
    }

    __syncthreads();
    if (wid == 0) TCGEN05_DEALLOC(tmem, 256);
}

// ---------------------------------------------------------------------------
// elementwise bf16 hi/lo split: fp32 -> (hi, lo)
// ---------------------------------------------------------------------------
__global__ void __launch_bounds__(256)
split_bf16(const float* __restrict__ in, __nv_bfloat16* __restrict__ ohi,
           __nv_bfloat16* __restrict__ olo, size_t n4)
{
    size_t i = (size_t)blockIdx.x * blockDim.x + threadIdx.x;
    size_t stride = (size_t)gridDim.x * blockDim.x;
    for (; i < n4; i += stride) {
        float4 v = ((const float4*)in)[i];
        float hx = bf16hi(v.x), hy = bf16hi(v.y), hz = bf16hi(v.z), hw = bf16hi(v.w);
        ((uint2*)ohi)[i] = make_uint2(bf16pack(v.x, v.y), bf16pack(v.z, v.w));
        ((uint2*)olo)[i] = make_uint2(bf16pack(v.x - hx, v.y - hy),
                                      bf16pack(v.z - hz, v.w - hw));
    }
}

// ---------------------------------------------------------------------------
// merged weight prep: all 4 transpose+split jobs in one launch.
// ---------------------------------------------------------------------------
__global__ void __launch_bounds__(256)
weights_prep(const float* __restrict__ W_in, const float* __restrict__ W_fwd,
             const float* __restrict__ W_bwd, const float* __restrict__ W_out,
             __nv_bfloat16* __restrict__ w1h, __nv_bfloat16* __restrict__ w1l,
             __nv_bfloat16* __restrict__ w2h, __nv_bfloat16* __restrict__ w2l,
             __nv_bfloat16* __restrict__ w3h, __nv_bfloat16* __restrict__ w3l)
{
    int id = blockIdx.x;
    const float* in;
    __nv_bfloat16 *oh, *ol;
    int R, C, bx, by;
    if (id < 512)       { in = W_in;  oh = w1h; ol = w1l; R = D_DIM;  C = DI_DIM; bx = id & 7;  by = id >> 3; }
    else if (id < 640)  { id -= 512; in = W_fwd; oh = w2h; ol = w2l; R = DI_DIM; C = 512; bx = id & 15; by = id >> 4; }
    else if (id < 768)  { id -= 640; in = W_bwd; oh = w2h + (size_t)512 * DI_DIM;
                          ol = w2l + (size_t)512 * DI_DIM; R = DI_DIM; C = 512; bx = id & 15; by = id >> 4; }
    else                { id -= 768; in = W_out; oh = w3h; ol = w3l; R = 512; C = D_DIM; bx = id & 63; by = id >> 6; }

    __shared__ float t[32][33];
    int c0 = bx * 32, r0 = by * 32;
    int tx = threadIdx.x & 31, ty = threadIdx.x >> 5;
#pragma unroll
    for (int i = 0; i < 32; i += 8)
        t[ty + i][tx] = in[(size_t)(r0 + ty + i) * C + c0 + tx];
    __syncthreads();
#pragma unroll
    for (int i = 0; i < 32; i += 8) {
        float v = t[tx][ty + i];
        float h = bf16hi(v);
        size_t off = (size_t)(c0 + ty + i) * R + r0 + tx;
        oh[off] = __float2bfloat16_rn(v);
        ol[off] = __float2bfloat16_rn(v - h);
    }
}

// ---------------------------------------------------------------------------
// 32x32 tiled transpose + bf16 split: in[R][C] fp32 -> hi/lo bf16 [C][R]
// ---------------------------------------------------------------------------
__global__ void __launch_bounds__(256)
transpose_split_bf16(const float* __restrict__ in, __nv_bfloat16* __restrict__ oh,
                     __nv_bfloat16* __restrict__ ol, int R, int C)
{
    __shared__ float t[32][33];
    int c0 = blockIdx.x * 32, r0 = blockIdx.y * 32;
    int tx = threadIdx.x, ty = threadIdx.y;
#pragma unroll
    for (int i = 0; i < 32; i += 8)
        t[ty + i][tx] = in[(size_t)(r0 + ty + i) * C + c0 + tx];
    __syncthreads();
#pragma unroll
    for (int i = 0; i < 32; i += 8) {
        float v = t[tx][ty + i];
        float h = bf16hi(v);
        size_t off = (size_t)(c0 + ty + i) * R + r0 + tx;
        oh[off] = __float2bfloat16_rn(v);
        ol[off] = __float2bfloat16_rn(v - h);
    }
}

// ---------------------------------------------------------------------------
// Gated linear scan: block per (channel, batch, dir)
// ---------------------------------------------------------------------------
__global__ __launch_bounds__(256)
void scan_kernel()
{
    int d = blockIdx.x, bb = blockIdx.y, dir = blockIdx.z;
    const float* dptr = &g_dg[(size_t)(dir * 512 + d)       * M_TOTAL + bb * L_SEQ];
    const float* gptr = &g_dg[(size_t)(dir * 512 + 256 + d) * M_TOTAL + bb * L_SEQ];
    float*       hptr = &g_h [(size_t)(dir * 256 + d)       * M_TOTAL + bb * L_SEQ];

    int tid = threadIdx.x;
    int base = (dir == 0) ? tid * 16 : (L_SEQ - 16 * (tid + 1));

    float tmpd[16], tmpg[16];
#pragma unroll
    for (int q = 0; q < 4; q++) {
        *(float4*)&tmpd[q * 4] = *(const float4*)&dptr[base + q * 4];
        *(float4*)&tmpg[q * 4] = *(const float4*)&gptr[base + q * 4];
    }
    float dl[16], gt[16];
#pragma unroll
    for (int e = 0; e < 16; e++) {
        int src = (dir == 0) ? e : (15 - e);
        dl[e] = tmpd[src];
        gt[e] = tmpg[src];
    }

    float Aseg = 1.f, Bseg = 0.f;
#pragma unroll
    for (int e = 0; e < 16; e++) {
        Aseg = Aseg * dl[e];
        Bseg = fmaf(Bseg, dl[e], gt[e]);
    }

    __shared__ float sA[256], sB[256];
    sA[tid] = Aseg; sB[tid] = Bseg;
    __syncthreads();
#pragma unroll
    for (int off = 1; off < 256; off <<= 1) {
        float pA = 0.f, pB = 0.f;
        bool has = (tid >= off);
        if (has) { pA = sA[tid - off]; pB = sB[tid - off]; }
        __syncthreads();
        if (has) {
            float Ac = sA[tid], Bc = sB[tid];
            sA[tid] = Ac * pA;
            sB[tid] = fmaf(Ac, pB, Bc);
        }
        __syncthreads();
    }

    float h = (tid == 0) ? 0.f : sB[tid - 1];
    float hv[16];
#pragma unroll
    for (int e = 0; e < 16; e++) {
        h = fmaf(h, dl[e], gt[e]);
        hv[e] = h;
    }

    float outv[16];
#pragma unroll
    for (int q = 0; q < 16; q++)
        outv[q] = (dir == 0) ? hv[q] : hv[15 - q];
#pragma unroll
    for (int q = 0; q < 4; q++)
        *(float4*)&hptr[base + q * 4] =
            make_float4(outv[q * 4], outv[q * 4 + 1], outv[q * 4 + 2], outv[q * 4 + 3]);
}

// ---------------------------------------------------------------------------
// LayerNorm over D=2048 per row
// ---------------------------------------------------------------------------
__global__ __launch_bounds__(256)
void ln_kernel(const float* __restrict__ gamma, const float* __restrict__ beta,
               float* __restrict__ out)
{
    int row = blockIdx.x;
    int tid = threadIdx.x;
    const float* yrow = &g_out[(size_t)row * D_DIM];

    float v[8];
    *(float4*)&v[0] = *(const float4*)&yrow[tid * 8];
    *(float4*)&v[4] = *(const float4*)&yrow[tid * 8 + 4];

    float s = 0.f, s2 = 0.f;
#pragma unroll
    for (int e = 0; e < 8; e++) { s += v[e]; s2 = fmaf(v[e], v[e], s2); }

#pragma unroll
    for (int o = 16; o > 0; o >>= 1) {
        s  += __shfl_xor_sync(0xffffffffu, s,  o);
        s2 += __shfl_xor_sync(0xffffffffu, s2, o);
    }
    __shared__ float sh[16];
    int w = tid >> 5, lane = tid & 31;
    if (lane == 0) { sh[w] = s; sh[8 + w] = s2; }
    __syncthreads();
    float S = 0.f, S2 = 0.f;
    if (lane < 8) { S = sh[lane]; S2 = sh[8 + lane]; }
#pragma unroll
    for (int o = 4; o > 0; o >>= 1) {
        S  += __shfl_xor_sync(0xffffffffu, S,  o);
        S2 += __shfl_xor_sync(0xffffffffu, S2, o);
    }
    S  = __shfl_sync(0xffffffffu, S,  0);
    S2 = __shfl_sync(0xffffffffu, S2, 0);

    const float invD = 1.f / (float)D_DIM;
    float mu = S * invD;
    float var = fmaf(S2, invD, -mu * mu);
    float inv = rsqrtf(var + LN_EPS);

    float g[8], be[8];
    *(float4*)&g[0]  = *(const float4*)&gamma[tid * 8];
    *(float4*)&g[4]  = *(const float4*)&gamma[tid * 8 + 4];
    *(float4*)&be[0] = *(const float4*)&beta[tid * 8];
    *(float4*)&be[4] = *(const float4*)&beta[tid * 8 + 4];

    float r[8];
#pragma unroll
    for (int e = 0; e < 8; e++)
        r[e] = fmaf((v[e] - mu) * inv, g[e], be[e]);

    float* orow = &out[(size_t)row * D_DIM];
    *(float4*)&orow[tid * 8]     = make_float4(r[0], r[1], r[2], r[3]);
    *(float4*)&orow[tid * 8 + 4] = make_float4(r[4], r[5], r[6], r[7]);
}

// ---------------------------------------------------------------------------
extern "C" void kernel_launch(void* const* d_in, const int* in_sizes, int n_in,
                              void* d_out, int out_size)
{
    const float* x     = (const float*)d_in[0];
    const float* W_in  = (const float*)d_in[1];
    const float* W_fwd = (const float*)d_in[2];
    const float* W_bwd = (const float*)d_in[3];
    const float* W_out = (const float*)d_in[4];
    const float* gamma = (const float*)d_in[5];
    const float* beta  = (const float*)d_in[6];
    float* out = (float*)d_out;

    float *zp, *dgp, *hp, *op;
    __nv_bfloat16 *xh, *xl, *zh, *zl, *hh, *hl, *w1h, *w1l, *w2h, *w2l, *w3h, *w3l;
    cudaGetSymbolAddress((void**)&zp,  g_z);
    cudaGetSymbolAddress((void**)&dgp, g_dg);
    cudaGetSymbolAddress((void**)&hp,  g_h);
    cudaGetSymbolAddress((void**)&op,  g_out);
    cudaGetSymbolAddress((void**)&xh,  g_xh);
    cudaGetSymbolAddress((void**)&xl,  g_xl);
    cudaGetSymbolAddress((void**)&zh,  g_zh);
    cudaGetSymbolAddress((void**)&zl,  g_zl);
    cudaGetSymbolAddress((void**)&hh,  g_hh);
    cudaGetSymbolAddress((void**)&hl,  g_hl);
    cudaGetSymbolAddress((void**)&w1h, g_w1h);
    cudaGetSymbolAddress((void**)&w1l, g_w1l);
    cudaGetSymbolAddress((void**)&w2h, g_w2h);
    cudaGetSymbolAddress((void**)&w2l, g_w2l);
    cudaGetSymbolAddress((void**)&w3h, g_w3h);
    cudaGetSymbolAddress((void**)&w3l, g_w3l);

    cudaFuncSetAttribute((const void*)gemm_bf16x3<0>,
                         cudaFuncAttributeMaxDynamicSharedMemorySize, GSMEM);
    cudaFuncSetAttribute((const void*)gemm_bf16x3<2>,
                         cudaFuncAttributeMaxDynamicSharedMemorySize, GSMEM);
    cudaFuncSetAttribute((const void*)gemm_bf16x3<3>,
                         cudaFuncAttributeMaxDynamicSharedMemorySize, GSMEM);

    // operand preparation
    split_bf16<<<2048, 256>>>(x, xh, xl, (size_t)M_TOTAL * D_DIM / 4);
    weights_prep<<<1792, 256>>>(W_in, W_fwd, W_bwd, W_out,
                                w1h, w1l, w2h, w2l, w3h, w3l);

    // z = x @ W_in  (fp32 + bf16 hi/lo epilogue)
    gemm_bf16x3<0><<<dim3(1, M_TOTAL / 128), 256, GSMEM>>>(
        xh, xl, w1h, w1l, zp, zh, zl, nullptr, DI_DIM, D_DIM);

    // dg^T = act(z @ [W_fwd|W_bwd])^T
    gemm_bf16x3<2><<<dim3(4, M_TOTAL / 128), 256, GSMEM>>>(
        zh, zl, w2h, w2l, dgp, nullptr, nullptr, zp, 1024, DI_DIM);

    // bidirectional gated scans -> h^T
    scan_kernel<<<dim3(DI_DIM, 4, 2), 256>>>();

    // h^T -> h row-major bf16 hi/lo
    transpose_split_bf16<<<dim3(M_TOTAL / 32, 512 / 32), dim3(32, 8)>>>(hp, hh, hl, 512, M_TOTAL);

    // y = h @ W_out + x
    gemm_bf16x3<3><<<dim3(8, M_TOTAL / 128), 256, GSMEM>>>(
        hh, hl, w3h, w3l, op, nullptr, nullptr, x, D_DIM, 512);

    // LayerNorm
    ln_kernel<<<M_TOTAL, 256>>>(gamma, beta, out);
}